// round 1
// baseline (speedup 1.0000x reference)
#include <cuda_runtime.h>
#include <cuda_bf16.h>
#include <math.h>

// Problem constants (fixed by the dataset):
//   query  [B=4, Q=512, D=1024]
//   memory [B=4, K=4096, D=1024]
//   bias   [B=4, K=4096]
//   Wq,Wk,Wv,Wo [1024,1024]
//   out    [4, 512, 1024] fp32
#define BB 4
#define QL 512
#define KL 4096
#define DD 1024
#define NH 16
#define DH 64

// ---------------- scratch (static device arrays; no runtime allocation) ----
__device__ float g_q[(size_t)BB * QL * DD];     // 8 MB
__device__ float g_k[(size_t)BB * KL * DD];     // 64 MB
__device__ float g_v[(size_t)BB * KL * DD];     // 64 MB
__device__ float g_attn[(size_t)BB * QL * DD];  // 8 MB

// ---------------- generic tiled fp32 GEMM: C[M,N] = A[M,K] * B[K,N] --------
// BM=BN=64, BK=16, 256 threads, 4x4 register tile per thread.
__global__ __launch_bounds__(256) void gemm_kernel(
    const float* __restrict__ A, const float* __restrict__ B,
    float* __restrict__ C, int M, int N, int K)
{
    __shared__ float As[16 * 65];  // As[kk*65 + row]  (A tile transposed)
    __shared__ float Bs[16 * 65];  // Bs[kk*65 + col]

    const int t  = threadIdx.x;
    const int tx = t & 15;
    const int ty = t >> 4;
    const int n0 = blockIdx.x * 64;
    const int m0 = blockIdx.y * 64;

    float acc[4][4] = {};

    for (int k0 = 0; k0 < K; k0 += 16) {
        // load A 64x16 -> transposed smem
        #pragma unroll
        for (int i = 0; i < 4; ++i) {
            int idx = t + i * 256;
            int row = idx >> 4;
            int kk  = idx & 15;
            As[kk * 65 + row] = A[(size_t)(m0 + row) * K + k0 + kk];
        }
        // load B 16x64 -> smem (coalesced)
        #pragma unroll
        for (int i = 0; i < 4; ++i) {
            int idx = t + i * 256;
            int kk  = idx >> 6;
            int col = idx & 63;
            Bs[kk * 65 + col] = B[(size_t)(k0 + kk) * N + n0 + col];
        }
        __syncthreads();

        #pragma unroll
        for (int kk = 0; kk < 16; ++kk) {
            float a[4], b[4];
            #pragma unroll
            for (int i = 0; i < 4; ++i) a[i] = As[kk * 65 + ty * 4 + i];
            #pragma unroll
            for (int j = 0; j < 4; ++j) b[j] = Bs[kk * 65 + tx * 4 + j];
            #pragma unroll
            for (int i = 0; i < 4; ++i)
                #pragma unroll
                for (int j = 0; j < 4; ++j)
                    acc[i][j] += a[i] * b[j];
        }
        __syncthreads();
    }

    #pragma unroll
    for (int i = 0; i < 4; ++i)
        #pragma unroll
        for (int j = 0; j < 4; ++j)
            C[(size_t)(m0 + ty * 4 + i) * N + n0 + tx * 4 + j] = acc[i][j];
}

// ---------------- fused biased-softmax attention (flash style) -------------
// One block per (b, h, 64-row q-tile). Streams K/V in 64-wide tiles with
// online softmax; never materializes the BHQK score tensor.
// Dynamic smem layout (floats):
//   Qs[64][65] transposed (Qs[d*65 + r])
//   Ks[64][65] transposed (Ks[d*65 + c])
//   Vs[64][65] direct     (Vs[c*65 + d])
//   Ps[64][65] transposed (Ps[c*65 + r])
//   sB[64] bias tile
#define ATT_SMEM_FLOATS (4 * 64 * 65 + 64)
#define ATT_SMEM_BYTES  (ATT_SMEM_FLOATS * 4)

__global__ __launch_bounds__(256) void attn_kernel(
    const float* __restrict__ q, const float* __restrict__ k,
    const float* __restrict__ v, const float* __restrict__ bias,
    float* __restrict__ out)
{
    extern __shared__ float sm[];
    float* Qs = sm;
    float* Ks = Qs + 64 * 65;
    float* Vs = Ks + 64 * 65;
    float* Ps = Vs + 64 * 65;
    float* sB = Ps + 64 * 65;

    const int qt = blockIdx.x;   // q tile (0..7)
    const int h  = blockIdx.y;   // head
    const int b  = blockIdx.z;   // batch
    const int t  = threadIdx.x;
    const int tx = t & 15;
    const int ty = t >> 4;
    const int q0 = qt * 64;
    const float scale = 0.125f;  // dh^-0.5, dh=64

    const float* qbase = q + ((size_t)(b * QL + q0)) * DD + h * DH;
    const float* kbase = k + ((size_t)b * KL) * DD + h * DH;
    const float* vbase = v + ((size_t)b * KL) * DD + h * DH;
    const float* bbase = bias + (size_t)b * KL;

    // load Q tile transposed
    #pragma unroll
    for (int i = 0; i < 16; ++i) {
        int idx = t + i * 256;
        int r = idx >> 6;
        int d = idx & 63;
        Qs[d * 65 + r] = qbase[(size_t)r * DD + d];
    }

    float o[4][4] = {};
    float m[4], l[4];
    #pragma unroll
    for (int i = 0; i < 4; ++i) { m[i] = -1e30f; l[i] = 0.0f; }

    __syncthreads();

    for (int kt = 0; kt < KL / 64; ++kt) {
        const int kk0 = kt * 64;

        // load K (transposed), V (direct), bias tile
        #pragma unroll
        for (int i = 0; i < 16; ++i) {
            int idx = t + i * 256;
            int c = idx >> 6;
            int d = idx & 63;
            float kval = kbase[(size_t)(kk0 + c) * DD + d];
            float vval = vbase[(size_t)(kk0 + c) * DD + d];
            Ks[d * 65 + c] = kval;
            Vs[c * 65 + d] = vval;
        }
        if (t < 64) sB[t] = bbase[kk0 + t];
        __syncthreads();

        // S = (Q K^T) * scale + bias
        float s[4][4] = {};
        #pragma unroll 16
        for (int d = 0; d < 64; ++d) {
            float a[4], bb[4];
            #pragma unroll
            for (int i = 0; i < 4; ++i) a[i]  = Qs[d * 65 + ty * 4 + i];
            #pragma unroll
            for (int j = 0; j < 4; ++j) bb[j] = Ks[d * 65 + tx * 4 + j];
            #pragma unroll
            for (int i = 0; i < 4; ++i)
                #pragma unroll
                for (int j = 0; j < 4; ++j)
                    s[i][j] += a[i] * bb[j];
        }
        #pragma unroll
        for (int i = 0; i < 4; ++i)
            #pragma unroll
            for (int j = 0; j < 4; ++j)
                s[i][j] = s[i][j] * scale + sB[tx * 4 + j];

        // online softmax: per-row max/sum across the 16 tx lanes
        #pragma unroll
        for (int i = 0; i < 4; ++i) {
            float mt = fmaxf(fmaxf(s[i][0], s[i][1]), fmaxf(s[i][2], s[i][3]));
            #pragma unroll
            for (int off = 1; off < 16; off <<= 1)
                mt = fmaxf(mt, __shfl_xor_sync(0xffffffffu, mt, off));
            float mnew = fmaxf(m[i], mt);
            float corr = __expf(m[i] - mnew);
            float rs = 0.0f;
            #pragma unroll
            for (int j = 0; j < 4; ++j) {
                s[i][j] = __expf(s[i][j] - mnew);
                rs += s[i][j];
            }
            #pragma unroll
            for (int off = 1; off < 16; off <<= 1)
                rs += __shfl_xor_sync(0xffffffffu, rs, off);
            l[i] = l[i] * corr + rs;
            m[i] = mnew;
            #pragma unroll
            for (int j = 0; j < 4; ++j) o[i][j] *= corr;
        }

        // write P (transposed) to smem
        #pragma unroll
        for (int i = 0; i < 4; ++i)
            #pragma unroll
            for (int j = 0; j < 4; ++j)
                Ps[(tx * 4 + j) * 65 + ty * 4 + i] = s[i][j];
        __syncthreads();

        // O += P @ V
        #pragma unroll 16
        for (int c = 0; c < 64; ++c) {
            float p[4], vv[4];
            #pragma unroll
            for (int i = 0; i < 4; ++i) p[i]  = Ps[c * 65 + ty * 4 + i];
            #pragma unroll
            for (int j = 0; j < 4; ++j) vv[j] = Vs[c * 65 + tx * 4 + j];
            #pragma unroll
            for (int i = 0; i < 4; ++i)
                #pragma unroll
                for (int j = 0; j < 4; ++j)
                    o[i][j] += p[i] * vv[j];
        }
        __syncthreads();  // protect Ks/Vs/Ps before next iteration's loads
    }

    // normalize and store to [B*Q, D] layout (head h occupies cols h*64..h*64+63)
    #pragma unroll
    for (int i = 0; i < 4; ++i) {
        float inv = 1.0f / l[i];
        #pragma unroll
        for (int j = 0; j < 4; ++j) {
            out[(size_t)(b * QL + q0 + ty * 4 + i) * DD + h * DH + tx * 4 + j] =
                o[i][j] * inv;
        }
    }
}

// ---------------- host launch ----------------------------------------------
extern "C" void kernel_launch(void* const* d_in, const int* in_sizes, int n_in,
                              void* d_out, int out_size)
{
    const float* query  = (const float*)d_in[0];
    const float* memory = (const float*)d_in[1];
    const float* bias   = (const float*)d_in[2];
    const float* Wq     = (const float*)d_in[3];
    const float* Wk     = (const float*)d_in[4];
    const float* Wv     = (const float*)d_in[5];
    const float* Wo     = (const float*)d_in[6];
    float* out = (float*)d_out;

    float *pq, *pk, *pv, *pattn;
    cudaGetSymbolAddress((void**)&pq,    g_q);
    cudaGetSymbolAddress((void**)&pk,    g_k);
    cudaGetSymbolAddress((void**)&pv,    g_v);
    cudaGetSymbolAddress((void**)&pattn, g_attn);

    static int smem_set = 0;
    if (!smem_set) {
        cudaFuncSetAttribute(attn_kernel,
                             cudaFuncAttributeMaxDynamicSharedMemorySize,
                             ATT_SMEM_BYTES);
        smem_set = 1;
    }

    dim3 thr(256);

    // Q projection: [2048,1024] @ [1024,1024]
    {
        dim3 grid(DD / 64, (BB * QL) / 64);
        gemm_kernel<<<grid, thr>>>(query, Wq, pq, BB * QL, DD, DD);
    }
    // K projection: [16384,1024] @ [1024,1024]
    {
        dim3 grid(DD / 64, (BB * KL) / 64);
        gemm_kernel<<<grid, thr>>>(memory, Wk, pk, BB * KL, DD, DD);
    }
    // V projection
    {
        dim3 grid(DD / 64, (BB * KL) / 64);
        gemm_kernel<<<grid, thr>>>(memory, Wv, pv, BB * KL, DD, DD);
    }
    // fused attention
    {
        dim3 grid(QL / 64, NH, BB);
        attn_kernel<<<grid, thr, ATT_SMEM_BYTES>>>(pq, pk, pv, bias, pattn);
    }
    // O projection -> output
    {
        dim3 grid(DD / 64, (BB * QL) / 64);
        gemm_kernel<<<grid, thr>>>(pattn, Wo, out, BB * QL, DD, DD);
    }
}

// round 3
// speedup vs baseline: 3.6343x; 3.6343x over previous
#include <cuda_runtime.h>
#include <cuda_bf16.h>
#include <math.h>
#include <stdint.h>

// Problem constants:
//   query [4,512,1024], memory [4,4096,1024], bias [4,4096]
//   Wq,Wk,Wv,Wo [1024,1024] -> out [4,512,1024] fp32
#define BB 4
#define QL 512
#define KL 4096
#define DD 1024
#define NH 16
#define DH 64

typedef __nv_bfloat16 bf16;

// ---------------- scratch (static device arrays) ---------------------------
__device__ __align__(128) bf16 gi_qhi[(size_t)BB * QL * DD];
__device__ __align__(128) bf16 gi_qlo[(size_t)BB * QL * DD];
__device__ __align__(128) bf16 gi_mhi[(size_t)BB * KL * DD];
__device__ __align__(128) bf16 gi_mlo[(size_t)BB * KL * DD];
__device__ __align__(128) bf16 g_wthi[4 * (size_t)DD * DD];
__device__ __align__(128) bf16 g_wtlo[4 * (size_t)DD * DD];
__device__ __align__(128) bf16 g_qhi[(size_t)BB * QL * DD];
__device__ __align__(128) bf16 g_qlo[(size_t)BB * QL * DD];
__device__ __align__(128) bf16 g_khi[(size_t)BB * KL * DD];
__device__ __align__(128) bf16 g_klo[(size_t)BB * KL * DD];
__device__ __align__(128) bf16 g_vhi[(size_t)BB * KL * DD];
__device__ __align__(128) bf16 g_vlo[(size_t)BB * KL * DD];
__device__ __align__(128) bf16 g_ahi[(size_t)BB * QL * DD];
__device__ __align__(128) bf16 g_alo[(size_t)BB * QL * DD];

// ---------------- PTX helpers (baseline sm_80+ features only) ---------------
__device__ __forceinline__ uint32_t smem_u32(const void* p) {
    uint32_t a;
    asm("{ .reg .u64 t; cvta.to.shared.u64 t, %1; cvt.u32.u64 %0, t; }" : "=r"(a) : "l"(p));
    return a;
}
__device__ __forceinline__ void cp16(uint32_t dst, const void* src) {
    asm volatile("cp.async.cg.shared.global [%0], [%1], 16;" :: "r"(dst), "l"(src));
}
#define CP_COMMIT() asm volatile("cp.async.commit_group;" ::: "memory")
#define CP_WAIT1()  asm volatile("cp.async.wait_group 1;" ::: "memory")
#define CP_WAIT0()  asm volatile("cp.async.wait_group 0;" ::: "memory")

__device__ __forceinline__ void ldsm_x4(uint32_t (&r)[4], uint32_t addr) {
    asm volatile("ldmatrix.sync.aligned.m8n8.x4.shared.b16 {%0,%1,%2,%3}, [%4];"
        : "=r"(r[0]), "=r"(r[1]), "=r"(r[2]), "=r"(r[3]) : "r"(addr));
}
__device__ __forceinline__ void ldsm_x2(uint32_t (&r)[2], uint32_t addr) {
    asm volatile("ldmatrix.sync.aligned.m8n8.x2.shared.b16 {%0,%1}, [%2];"
        : "=r"(r[0]), "=r"(r[1]) : "r"(addr));
}
__device__ __forceinline__ void ldsm_x2t(uint32_t (&r)[2], uint32_t addr) {
    asm volatile("ldmatrix.sync.aligned.m8n8.x2.trans.shared.b16 {%0,%1}, [%2];"
        : "=r"(r[0]), "=r"(r[1]) : "r"(addr));
}
__device__ __forceinline__ void mma_bf16(float (&d)[4], const uint32_t (&a)[4],
                                         const uint32_t (&b)[2]) {
    asm volatile(
        "mma.sync.aligned.m16n8k16.row.col.f32.bf16.bf16.f32 "
        "{%0,%1,%2,%3}, {%4,%5,%6,%7}, {%8,%9}, {%0,%1,%2,%3};"
        : "+f"(d[0]), "+f"(d[1]), "+f"(d[2]), "+f"(d[3])
        : "r"(a[0]), "r"(a[1]), "r"(a[2]), "r"(a[3]), "r"(b[0]), "r"(b[1]));
}
__device__ __forceinline__ uint32_t packbf(float a, float b) {
    __nv_bfloat162 t = __floats2bfloat162_rn(a, b);
    return *reinterpret_cast<uint32_t*>(&t);
}

// FFMA-only exp2 (floor + deg-6 Taylor of 2^f, rel err ~1e-5); avoids MUFU.
__device__ __forceinline__ float fexp2(float x) {
    x = fminf(fmaxf(x, -126.f), 126.f);
    float fl = floorf(x);
    float f = x - fl;
    float p = 1.54035304e-4f;
    p = fmaf(p, f, 1.33335581e-3f);
    p = fmaf(p, f, 9.61812911e-3f);
    p = fmaf(p, f, 5.55041087e-2f);
    p = fmaf(p, f, 2.40226507e-1f);
    p = fmaf(p, f, 6.93147181e-1f);
    p = fmaf(p, f, 1.0f);
    return p * __int_as_float(((int)fl + 127) << 23);
}

// ---------------- split-bf16 MMA GEMM ---------------------------------------
// C[M,1024] = A[M,1024] @ W[1024,1024], with A as hi/lo bf16 [M,K] and W^T
// as hi/lo bf16 [N,K]. 3-pass split MMA: Ahi*Bhi + Ahi*Blo + Alo*Bhi.
// CTA = 128x128 tile, BK=32, 256 threads (8 warps, 4x2), cp.async 2-stage.
// MODE 0: fp32 out. MODE 1: split hi/lo bf16 out.
#define GP 80            // smem row pitch bytes (32 bf16 cols + pad) - conflict free
#define GMATB (128 * GP) // 10240 B per matrix tile
#define GSTAGE (4 * GMATB)
#define GEMM_SMEM (2 * GSTAGE)

__device__ __forceinline__ void gemm_load_stage(
    uint32_t sb, int st, int t,
    const bf16* __restrict__ Ahi, const bf16* __restrict__ Alo,
    const bf16* __restrict__ Bhi, const bf16* __restrict__ Blo,
    int m0, int n0, int k0)
{
    uint32_t base = sb + st * GSTAGE;
    #pragma unroll
    for (int i = 0; i < 2; ++i) {
        int ch = t + i * 256;          // 512 chunks: 128 rows x 4 (16B) segs
        int row = ch >> 2, seg = ch & 3;
        size_t ga = (size_t)(m0 + row) * DD + k0 + seg * 8;
        uint32_t d = row * GP + seg * 16;
        cp16(base + d, Ahi + ga);
        cp16(base + GMATB + d, Alo + ga);
    }
    #pragma unroll
    for (int i = 0; i < 2; ++i) {
        int ch = t + i * 256;
        int row = ch >> 2, seg = ch & 3;
        size_t ga = (size_t)(n0 + row) * DD + k0 + seg * 8;
        uint32_t d = row * GP + seg * 16;
        cp16(base + 2 * GMATB + d, Bhi + ga);
        cp16(base + 3 * GMATB + d, Blo + ga);
    }
}

template <int MODE>
__global__ __launch_bounds__(256, 2) void gemm_mma(
    const bf16* __restrict__ Ahi, const bf16* __restrict__ Alo,
    const bf16* __restrict__ Bhi, const bf16* __restrict__ Blo,
    float* __restrict__ Cf, bf16* __restrict__ Chi, bf16* __restrict__ Clo)
{
    extern __shared__ char smem[];
    const uint32_t sb = smem_u32(smem);
    const int t = threadIdx.x;
    const int lane = t & 31, wid = t >> 5;
    const int wm = wid >> 1, wn = wid & 1;   // 4 x 2 warp grid
    const int n0 = blockIdx.x * 128, m0 = blockIdx.y * 128;

    float acc[2][8][4] = {};

    gemm_load_stage(sb, 0, t, Ahi, Alo, Bhi, Blo, m0, n0, 0);
    CP_COMMIT();
    gemm_load_stage(sb, 1, t, Ahi, Alo, Bhi, Blo, m0, n0, 32);
    CP_COMMIT();

    for (int it = 0; it < 32; ++it) {
        if (it < 31) { CP_WAIT1(); } else { CP_WAIT0(); }
        __syncthreads();

        const int st = it & 1;
        const uint32_t sAhi = sb + st * GSTAGE;
        const uint32_t sAlo = sAhi + GMATB;
        const uint32_t sBhi = sAhi + 2 * GMATB;
        const uint32_t sBlo = sAhi + 3 * GMATB;

        #pragma unroll
        for (int kt = 0; kt < 2; ++kt) {
            uint32_t ah[2][4], al[2][4];
            #pragma unroll
            for (int mt = 0; mt < 2; ++mt) {
                uint32_t row = wm * 32 + mt * 16 + (lane & 15);
                uint32_t col = kt * 16 + ((lane >> 4) << 3);
                ldsm_x4(ah[mt], sAhi + row * GP + col * 2);
                ldsm_x4(al[mt], sAlo + row * GP + col * 2);
            }
            #pragma unroll
            for (int nt = 0; nt < 8; ++nt) {
                uint32_t bh[2], bl[2];
                uint32_t row = wn * 64 + nt * 8 + (lane & 7);
                uint32_t col = kt * 16 + (lane & 8);
                ldsm_x2(bh, sBhi + row * GP + col * 2);
                ldsm_x2(bl, sBlo + row * GP + col * 2);
                #pragma unroll
                for (int mt = 0; mt < 2; ++mt) {
                    mma_bf16(acc[mt][nt], ah[mt], bh);
                    mma_bf16(acc[mt][nt], ah[mt], bl);
                    mma_bf16(acc[mt][nt], al[mt], bh);
                }
            }
        }
        __syncthreads();
        if (it + 2 < 32) {
            gemm_load_stage(sb, st, t, Ahi, Alo, Bhi, Blo, m0, n0, (it + 2) * 32);
            CP_COMMIT();
        } else {
            CP_COMMIT();  // keep per-thread group counts uniform
        }
    }

    // epilogue
    #pragma unroll
    for (int mt = 0; mt < 2; ++mt)
        #pragma unroll
        for (int nt = 0; nt < 8; ++nt) {
            int r = m0 + wm * 32 + mt * 16 + (lane >> 2);
            int c = n0 + wn * 64 + nt * 8 + (lane & 3) * 2;
            float v0 = acc[mt][nt][0], v1 = acc[mt][nt][1];
            float v2 = acc[mt][nt][2], v3 = acc[mt][nt][3];
            if (MODE == 0) {
                *reinterpret_cast<float2*>(Cf + (size_t)r * DD + c) = make_float2(v0, v1);
                *reinterpret_cast<float2*>(Cf + (size_t)(r + 8) * DD + c) = make_float2(v2, v3);
            } else {
                bf16 h0 = __float2bfloat16(v0), h1 = __float2bfloat16(v1);
                bf16 h2 = __float2bfloat16(v2), h3 = __float2bfloat16(v3);
                *reinterpret_cast<uint32_t*>(Chi + (size_t)r * DD + c) =
                    packbf(__bfloat162float(h0), __bfloat162float(h1));
                *reinterpret_cast<uint32_t*>(Chi + (size_t)(r + 8) * DD + c) =
                    packbf(__bfloat162float(h2), __bfloat162float(h3));
                *reinterpret_cast<uint32_t*>(Clo + (size_t)r * DD + c) =
                    packbf(v0 - __bfloat162float(h0), v1 - __bfloat162float(h1));
                *reinterpret_cast<uint32_t*>(Clo + (size_t)(r + 8) * DD + c) =
                    packbf(v2 - __bfloat162float(h2), v3 - __bfloat162float(h3));
            }
        }
}

// ---------------- fused attention on mma.sync --------------------------------
// CTA = (qtile of 128 rows, head, batch); 256 thr, 8 warps, warp = 16 q-rows.
// S = Q K^T (3-pass split), w = exp(S*scale + bias) via FFMA exp2 (no max
// subtraction; scores are bounded), O += P V (3-pass split, P hi/lo built
// in-register from the C-fragments). Final: O/l, stored as split bf16.
#define AP 144                    // smem pitch for 64-col bf16 tiles (+pad)
#define AMATB (128 * AP)          // 18432 B
#define A_SQHI 0
#define A_SQLO AMATB
#define A_KV0 (2 * AMATB)         // stage base: Khi,Klo,Vhi,Vlo
#define A_STAGE (4 * AMATB)
#define A_SBIAS (A_KV0 + 2 * A_STAGE)
#define ATT_SMEM (A_SBIAS + 2 * 512)

__device__ __forceinline__ void attn_load_kv(
    uint32_t sb, int st, int t,
    const bf16* __restrict__ khi, const bf16* __restrict__ klo,
    const bf16* __restrict__ vhi, const bf16* __restrict__ vlo,
    const float* __restrict__ bias, size_t krow0, int hcol, size_t boff)
{
    uint32_t base = sb + A_KV0 + st * A_STAGE;
    #pragma unroll
    for (int i = 0; i < 4; ++i) {
        int ch = t + i * 256;          // 1024 chunks: 128 rows x 8 segs
        int row = ch >> 3, seg = ch & 7;
        size_t ga = (krow0 + row) * DD + hcol + seg * 8;
        uint32_t d = row * AP + seg * 16;
        cp16(base + d, khi + ga);
        cp16(base + AMATB + d, klo + ga);
        cp16(base + 2 * AMATB + d, vhi + ga);
        cp16(base + 3 * AMATB + d, vlo + ga);
    }
    if (t < 32) cp16(sb + A_SBIAS + st * 512 + t * 16, bias + boff + t * 4);
}

__global__ __launch_bounds__(256) void attn_mma(
    const bf16* __restrict__ qhi, const bf16* __restrict__ qlo,
    const bf16* __restrict__ khi, const bf16* __restrict__ klo,
    const bf16* __restrict__ vhi, const bf16* __restrict__ vlo,
    const float* __restrict__ bias,
    bf16* __restrict__ ohi, bf16* __restrict__ olo)
{
    extern __shared__ char smem[];
    const uint32_t sb = smem_u32(smem);
    const int t = threadIdx.x;
    const int lane = t & 31, wid = t >> 5;
    const int qt = blockIdx.x, h = blockIdx.y, b = blockIdx.z;
    const int hcol = h * DH;
    const size_t qrow0 = (size_t)b * QL + qt * 128;
    const size_t krowb = (size_t)b * KL;
    const float C1 = 0.125f * 1.44269504f;   // scale * log2(e)
    const float C2 = 1.44269504f;

    // load Q tile (hi/lo)
    #pragma unroll
    for (int i = 0; i < 4; ++i) {
        int ch = t + i * 256;
        int row = ch >> 3, seg = ch & 7;
        size_t ga = (qrow0 + row) * DD + hcol + seg * 8;
        uint32_t d = row * AP + seg * 16;
        cp16(sb + A_SQHI + d, qhi + ga);
        cp16(sb + A_SQLO + d, qlo + ga);
    }
    attn_load_kv(sb, 0, t, khi, klo, vhi, vlo, bias, krowb, hcol, krowb);
    CP_COMMIT();
    attn_load_kv(sb, 1, t, khi, klo, vhi, vlo, bias, krowb + 128, hcol, krowb + 128);
    CP_COMMIT();

    CP_WAIT1();
    __syncthreads();

    // Q fragments (resident)
    uint32_t qh[4][4], ql[4][4];
    #pragma unroll
    for (int dt = 0; dt < 4; ++dt) {
        uint32_t row = wid * 16 + (lane & 15);
        uint32_t col = dt * 16 + ((lane >> 4) << 3);
        ldsm_x4(qh[dt], sb + A_SQHI + row * AP + col * 2);
        ldsm_x4(ql[dt], sb + A_SQLO + row * AP + col * 2);
    }

    float oacc[8][4] = {};
    float l0 = 0.f, l1 = 0.f;

    for (int it = 0; it < 32; ++it) {
        if (it > 0) {
            if (it < 31) { CP_WAIT1(); } else { CP_WAIT0(); }
            __syncthreads();
        }
        const int st = it & 1;
        const uint32_t sKhi = sb + A_KV0 + st * A_STAGE;
        const uint32_t sKlo = sKhi + AMATB;
        const uint32_t sVhi = sKhi + 2 * AMATB;
        const uint32_t sVlo = sKhi + 3 * AMATB;
        const uint32_t sBs  = sb + A_SBIAS + st * 512;

        // S = Q K^T  (3-pass split)
        float w[16][4] = {};
        #pragma unroll
        for (int dt = 0; dt < 4; ++dt) {
            #pragma unroll
            for (int nt = 0; nt < 16; ++nt) {
                uint32_t bh[2], bl[2];
                uint32_t row = nt * 8 + (lane & 7);
                uint32_t col = dt * 16 + (lane & 8);
                ldsm_x2(bh, sKhi + row * AP + col * 2);
                ldsm_x2(bl, sKlo + row * AP + col * 2);
                mma_bf16(w[nt], qh[dt], bh);
                mma_bf16(w[nt], qh[dt], bl);
                mma_bf16(w[nt], ql[dt], bh);
            }
        }

        // w = exp(S*scale + bias); accumulate row sums
        #pragma unroll
        for (int nt = 0; nt < 16; ++nt) {
            float2 bv = *reinterpret_cast<const float2*>(
                smem + A_SBIAS + st * 512 + (nt * 8 + (lane & 3) * 2) * 4);
            (void)sBs;
            w[nt][0] = fexp2(fmaf(w[nt][0], C1, bv.x * C2));
            w[nt][1] = fexp2(fmaf(w[nt][1], C1, bv.y * C2));
            w[nt][2] = fexp2(fmaf(w[nt][2], C1, bv.x * C2));
            w[nt][3] = fexp2(fmaf(w[nt][3], C1, bv.y * C2));
            l0 += w[nt][0] + w[nt][1];
            l1 += w[nt][2] + w[nt][3];
        }

        // O += P V  (3-pass split; P frags from C-layout registers)
        #pragma unroll
        for (int g = 0; g < 8; ++g) {
            float x0 = w[2 * g][0], x1 = w[2 * g][1], x2 = w[2 * g][2], x3 = w[2 * g][3];
            float y0 = w[2 * g + 1][0], y1 = w[2 * g + 1][1];
            float y2 = w[2 * g + 1][2], y3 = w[2 * g + 1][3];
            float hx0 = __bfloat162float(__float2bfloat16(x0));
            float hx1 = __bfloat162float(__float2bfloat16(x1));
            float hx2 = __bfloat162float(__float2bfloat16(x2));
            float hx3 = __bfloat162float(__float2bfloat16(x3));
            float hy0 = __bfloat162float(__float2bfloat16(y0));
            float hy1 = __bfloat162float(__float2bfloat16(y1));
            float hy2 = __bfloat162float(__float2bfloat16(y2));
            float hy3 = __bfloat162float(__float2bfloat16(y3));
            uint32_t phi[4], plo[4];
            phi[0] = packbf(hx0, hx1);            plo[0] = packbf(x0 - hx0, x1 - hx1);
            phi[1] = packbf(hx2, hx3);            plo[1] = packbf(x2 - hx2, x3 - hx3);
            phi[2] = packbf(hy0, hy1);            plo[2] = packbf(y0 - hy0, y1 - hy1);
            phi[3] = packbf(hy2, hy3);            plo[3] = packbf(y2 - hy2, y3 - hy3);
            #pragma unroll
            for (int nt = 0; nt < 8; ++nt) {
                uint32_t bh[2], bl[2];
                uint32_t row = g * 16 + (lane & 15);
                uint32_t col = nt * 8;
                ldsm_x2t(bh, sVhi + row * AP + col * 2);
                ldsm_x2t(bl, sVlo + row * AP + col * 2);
                mma_bf16(oacc[nt], phi, bh);
                mma_bf16(oacc[nt], phi, bl);
                mma_bf16(oacc[nt], plo, bh);
            }
        }

        __syncthreads();
        if (it + 2 < 32) {
            attn_load_kv(sb, st, t, khi, klo, vhi, vlo, bias,
                         krowb + (size_t)(it + 2) * 128, hcol,
                         krowb + (size_t)(it + 2) * 128);
            CP_COMMIT();
        } else {
            CP_COMMIT();
        }
    }

    // reduce l across the quad (lanes sharing a row) and normalize
    l0 += __shfl_xor_sync(0xffffffffu, l0, 1);
    l0 += __shfl_xor_sync(0xffffffffu, l0, 2);
    l1 += __shfl_xor_sync(0xffffffffu, l1, 1);
    l1 += __shfl_xor_sync(0xffffffffu, l1, 2);
    float inv0 = 1.0f / l0, inv1 = 1.0f / l1;

    size_t r0 = qrow0 + wid * 16 + (lane >> 2);
    size_t r1 = r0 + 8;
    #pragma unroll
    for (int nt = 0; nt < 8; ++nt) {
        int c = hcol + nt * 8 + (lane & 3) * 2;
        float v0 = oacc[nt][0] * inv0, v1 = oacc[nt][1] * inv0;
        float v2 = oacc[nt][2] * inv1, v3 = oacc[nt][3] * inv1;
        bf16 h0 = __float2bfloat16(v0), h1 = __float2bfloat16(v1);
        bf16 h2 = __float2bfloat16(v2), h3 = __float2bfloat16(v3);
        *reinterpret_cast<uint32_t*>(ohi + r0 * DD + c) =
            packbf(__bfloat162float(h0), __bfloat162float(h1));
        *reinterpret_cast<uint32_t*>(ohi + r1 * DD + c) =
            packbf(__bfloat162float(h2), __bfloat162float(h3));
        *reinterpret_cast<uint32_t*>(olo + r0 * DD + c) =
            packbf(v0 - __bfloat162float(h0), v1 - __bfloat162float(h1));
        *reinterpret_cast<uint32_t*>(olo + r1 * DD + c) =
            packbf(v2 - __bfloat162float(h2), v3 - __bfloat162float(h3));
    }
}

// ---------------- conversion kernels ----------------------------------------
__global__ void split4_kernel(const float4* __restrict__ x,
                              __nv_bfloat162* __restrict__ hi,
                              __nv_bfloat162* __restrict__ lo, int n4)
{
    int i = blockIdx.x * blockDim.x + threadIdx.x;
    if (i >= n4) return;
    float4 v = x[i];
    bf16 h0 = __float2bfloat16(v.x), h1 = __float2bfloat16(v.y);
    bf16 h2 = __float2bfloat16(v.z), h3 = __float2bfloat16(v.w);
    hi[2 * i]     = __nv_bfloat162(h0, h1);
    hi[2 * i + 1] = __nv_bfloat162(h2, h3);
    lo[2 * i]     = __floats2bfloat162_rn(v.x - __bfloat162float(h0),
                                          v.y - __bfloat162float(h1));
    lo[2 * i + 1] = __floats2bfloat162_rn(v.z - __bfloat162float(h2),
                                          v.w - __bfloat162float(h3));
}

// W[1024,1024] fp32 row-major -> W^T hi/lo bf16 [N,K]
__global__ void transpose_split_kernel(const float* __restrict__ W,
                                       bf16* __restrict__ Thi, bf16* __restrict__ Tlo)
{
    __shared__ float tl[32][33];
    const int tx = threadIdx.x, ty = threadIdx.y;
    const int n0 = blockIdx.x * 32, k0 = blockIdx.y * 32;
    #pragma unroll
    for (int i = 0; i < 4; ++i)
        tl[ty + i * 8][tx] = W[(size_t)(k0 + ty + i * 8) * DD + n0 + tx];
    __syncthreads();
    #pragma unroll
    for (int i = 0; i < 4; ++i) {
        float v = tl[tx][ty + i * 8];  // = W[k0+tx][n0+ty+i*8]
        bf16 hv = __float2bfloat16(v);
        size_t idx = (size_t)(n0 + ty + i * 8) * DD + k0 + tx;
        Thi[idx] = hv;
        Tlo[idx] = __float2bfloat16(v - __bfloat162float(hv));
    }
}

// ---------------- host launch -------------------------------------------------
extern "C" void kernel_launch(void* const* d_in, const int* in_sizes, int n_in,
                              void* d_out, int out_size)
{
    const float* query  = (const float*)d_in[0];
    const float* memory = (const float*)d_in[1];
    const float* bias   = (const float*)d_in[2];
    const float* W[4]   = {(const float*)d_in[3], (const float*)d_in[4],
                           (const float*)d_in[5], (const float*)d_in[6]};
    float* out = (float*)d_out;

    bf16 *iqh, *iql, *imh, *iml, *wth, *wtl;
    bf16 *qh, *qlp, *kh, *klp, *vh, *vlp, *ah, *alp;
    cudaGetSymbolAddress((void**)&iqh, gi_qhi);
    cudaGetSymbolAddress((void**)&iql, gi_qlo);
    cudaGetSymbolAddress((void**)&imh, gi_mhi);
    cudaGetSymbolAddress((void**)&iml, gi_mlo);
    cudaGetSymbolAddress((void**)&wth, g_wthi);
    cudaGetSymbolAddress((void**)&wtl, g_wtlo);
    cudaGetSymbolAddress((void**)&qh, g_qhi);
    cudaGetSymbolAddress((void**)&qlp, g_qlo);
    cudaGetSymbolAddress((void**)&kh, g_khi);
    cudaGetSymbolAddress((void**)&klp, g_klo);
    cudaGetSymbolAddress((void**)&vh, g_vhi);
    cudaGetSymbolAddress((void**)&vlp, g_vlo);
    cudaGetSymbolAddress((void**)&ah, g_ahi);
    cudaGetSymbolAddress((void**)&alp, g_alo);

    static int attr_set = 0;
    if (!attr_set) {
        cudaFuncSetAttribute(gemm_mma<0>, cudaFuncAttributeMaxDynamicSharedMemorySize,
                             GEMM_SMEM);
        cudaFuncSetAttribute(gemm_mma<1>, cudaFuncAttributeMaxDynamicSharedMemorySize,
                             GEMM_SMEM);
        cudaFuncSetAttribute(attn_mma, cudaFuncAttributeMaxDynamicSharedMemorySize,
                             ATT_SMEM);
        attr_set = 1;
    }

    // split inputs
    {
        int n4 = (BB * QL * DD) / 4;
        split4_kernel<<<n4 / 256, 256>>>((const float4*)query,
                                         (__nv_bfloat162*)iqh, (__nv_bfloat162*)iql, n4);
    }
    {
        int n4 = (BB * KL * DD) / 4;
        split4_kernel<<<n4 / 256, 256>>>((const float4*)memory,
                                         (__nv_bfloat162*)imh, (__nv_bfloat162*)iml, n4);
    }
    {
        dim3 thr(32, 8), grid(DD / 32, DD / 32);
        for (int i = 0; i < 4; ++i)
            transpose_split_kernel<<<grid, thr>>>(W[i], wth + (size_t)i * DD * DD,
                                                  wtl + (size_t)i * DD * DD);
    }

    // projections (split-bf16 epilogues for Q/K/V)
    {
        dim3 grid(DD / 128, (BB * QL) / 128);
        gemm_mma<1><<<grid, 256, GEMM_SMEM>>>(iqh, iql, wth, wtl, nullptr, qh, qlp);
    }
    {
        dim3 grid(DD / 128, (BB * KL) / 128);
        gemm_mma<1><<<grid, 256, GEMM_SMEM>>>(imh, iml, wth + (size_t)DD * DD,
                                              wtl + (size_t)DD * DD, nullptr, kh, klp);
        gemm_mma<1><<<grid, 256, GEMM_SMEM>>>(imh, iml, wth + 2 * (size_t)DD * DD,
                                              wtl + 2 * (size_t)DD * DD, nullptr, vh, vlp);
    }
    // attention
    {
        dim3 grid(QL / 128, NH, BB);
        attn_mma<<<grid, 256, ATT_SMEM>>>(qh, qlp, kh, klp, vh, vlp, bias, ah, alp);
    }
    // O projection -> fp32 out
    {
        dim3 grid(DD / 128, (BB * QL) / 128);
        gemm_mma<0><<<grid, 256, GEMM_SMEM>>>(ah, alp, wth + 3 * (size_t)DD * DD,
                                              wtl + 3 * (size_t)DD * DD, out, nullptr,
                                              nullptr);
    }
}

// round 4
// speedup vs baseline: 5.0421x; 1.3874x over previous
#include <cuda_runtime.h>
#include <cuda_fp16.h>
#include <math.h>
#include <stdint.h>

// Problem constants:
//   query [4,512,1024], memory [4,4096,1024], bias [4,4096]
//   Wq,Wk,Wv,Wo [1024,1024] -> out [4,512,1024] fp32
#define BB 4
#define QL 512
#define KL 4096
#define DD 1024
#define NH 16
#define DH 64

typedef __half half_t;

// ---------------- scratch (static device arrays) ---------------------------
__device__ __align__(128) half_t gi_q16[(size_t)BB * QL * DD];   // query fp16
__device__ __align__(128) half_t gi_m16[(size_t)BB * KL * DD];   // memory fp16
__device__ __align__(128) half_t g_wthi[4 * (size_t)DD * DD];    // W^T hi fp16
__device__ __align__(128) half_t g_wtlo[4 * (size_t)DD * DD];    // W^T lo fp16
__device__ __align__(128) half_t g_qhi[(size_t)BB * QL * DD];    // Q hi/lo (A-side of QK)
__device__ __align__(128) half_t g_qlo[(size_t)BB * QL * DD];
__device__ __align__(128) half_t g_k16[(size_t)BB * KL * DD];    // K single fp16
__device__ __align__(128) half_t g_v16[(size_t)BB * KL * DD];    // V single fp16
__device__ __align__(128) half_t g_a16[(size_t)BB * QL * DD];    // attn out fp16

// ---------------- PTX helpers (baseline sm_80+ features only) ---------------
__device__ __forceinline__ uint32_t smem_u32(const void* p) {
    uint32_t a;
    asm("{ .reg .u64 t; cvta.to.shared.u64 t, %1; cvt.u32.u64 %0, t; }" : "=r"(a) : "l"(p));
    return a;
}
__device__ __forceinline__ void cp16(uint32_t dst, const void* src) {
    asm volatile("cp.async.cg.shared.global [%0], [%1], 16;" :: "r"(dst), "l"(src));
}
#define CP_COMMIT() asm volatile("cp.async.commit_group;" ::: "memory")
#define CP_WAIT1()  asm volatile("cp.async.wait_group 1;" ::: "memory")
#define CP_WAIT0()  asm volatile("cp.async.wait_group 0;" ::: "memory")

__device__ __forceinline__ void ldsm_x4(uint32_t (&r)[4], uint32_t addr) {
    asm volatile("ldmatrix.sync.aligned.m8n8.x4.shared.b16 {%0,%1,%2,%3}, [%4];"
        : "=r"(r[0]), "=r"(r[1]), "=r"(r[2]), "=r"(r[3]) : "r"(addr));
}
__device__ __forceinline__ void ldsm_x2(uint32_t (&r)[2], uint32_t addr) {
    asm volatile("ldmatrix.sync.aligned.m8n8.x2.shared.b16 {%0,%1}, [%2];"
        : "=r"(r[0]), "=r"(r[1]) : "r"(addr));
}
__device__ __forceinline__ void ldsm_x2t(uint32_t (&r)[2], uint32_t addr) {
    asm volatile("ldmatrix.sync.aligned.m8n8.x2.trans.shared.b16 {%0,%1}, [%2];"
        : "=r"(r[0]), "=r"(r[1]) : "r"(addr));
}
__device__ __forceinline__ void mma_f16(float (&d)[4], const uint32_t (&a)[4],
                                        const uint32_t (&b)[2]) {
    asm volatile(
        "mma.sync.aligned.m16n8k16.row.col.f32.f16.f16.f32 "
        "{%0,%1,%2,%3}, {%4,%5,%6,%7}, {%8,%9}, {%0,%1,%2,%3};"
        : "+f"(d[0]), "+f"(d[1]), "+f"(d[2]), "+f"(d[3])
        : "r"(a[0]), "r"(a[1]), "r"(a[2]), "r"(a[3]), "r"(b[0]), "r"(b[1]));
}
__device__ __forceinline__ uint32_t packh(float a, float b) {
    __half2 t = __floats2half2_rn(a, b);
    return *reinterpret_cast<uint32_t*>(&t);
}

// FFMA-only exp2 (floor + deg-6 poly, rel err ~1e-5); avoids MUFU.
__device__ __forceinline__ float fexp2(float x) {
    x = fminf(fmaxf(x, -126.f), 126.f);
    float fl = floorf(x);
    float f = x - fl;
    float p = 1.54035304e-4f;
    p = fmaf(p, f, 1.33335581e-3f);
    p = fmaf(p, f, 9.61812911e-3f);
    p = fmaf(p, f, 5.55041087e-2f);
    p = fmaf(p, f, 2.40226507e-1f);
    p = fmaf(p, f, 6.93147181e-1f);
    p = fmaf(p, f, 1.0f);
    return p * __int_as_float(((int)fl + 127) << 23);
}

// ---------------- split-fp16 MMA GEMM ---------------------------------------
// C[M,1024] = A[M,1024] @ W[1024,1024]; A single fp16 [M,K], W^T split hi/lo
// fp16 [N,K]. 2-pass: A*Whi + A*Wlo. CTA = 128x128, BK=32, 256 thr (8 warps).
// MODE 0: fp32 out. MODE 1: single fp16 out. MODE 2: hi/lo fp16 out.
#define GP 80            // smem row pitch bytes (32 fp16 + pad), conflict free
#define GMATB (128 * GP) // 10240 B per matrix tile
#define GSTAGE (3 * GMATB)
#define GEMM_SMEM (2 * GSTAGE)

__device__ __forceinline__ void gemm_load_stage(
    uint32_t sb, int st, int t,
    const half_t* __restrict__ A,
    const half_t* __restrict__ Bhi, const half_t* __restrict__ Blo,
    int m0, int n0, int k0)
{
    uint32_t base = sb + st * GSTAGE;
    #pragma unroll
    for (int i = 0; i < 2; ++i) {
        int ch = t + i * 256;          // 512 chunks: 128 rows x 4 (16B) segs
        int row = ch >> 2, seg = ch & 3;
        uint32_t d = row * GP + seg * 16;
        cp16(base + d, A + (size_t)(m0 + row) * DD + k0 + seg * 8);
        size_t gb = (size_t)(n0 + row) * DD + k0 + seg * 8;
        cp16(base + GMATB + d, Bhi + gb);
        cp16(base + 2 * GMATB + d, Blo + gb);
    }
}

template <int MODE>
__global__ __launch_bounds__(256, 2) void gemm_mma(
    const half_t* __restrict__ A,
    const half_t* __restrict__ Bhi, const half_t* __restrict__ Blo,
    float* __restrict__ Cf, half_t* __restrict__ Ch, half_t* __restrict__ Cl)
{
    extern __shared__ char smem[];
    const uint32_t sb = smem_u32(smem);
    const int t = threadIdx.x;
    const int lane = t & 31, wid = t >> 5;
    const int wm = wid >> 1, wn = wid & 1;   // 4 x 2 warp grid
    const int n0 = blockIdx.x * 128, m0 = blockIdx.y * 128;

    float acc[2][8][4] = {};

    gemm_load_stage(sb, 0, t, A, Bhi, Blo, m0, n0, 0);
    CP_COMMIT();
    gemm_load_stage(sb, 1, t, A, Bhi, Blo, m0, n0, 32);
    CP_COMMIT();

    for (int it = 0; it < 32; ++it) {
        if (it < 31) { CP_WAIT1(); } else { CP_WAIT0(); }
        __syncthreads();

        const int st = it & 1;
        const uint32_t sA   = sb + st * GSTAGE;
        const uint32_t sBhi = sA + GMATB;
        const uint32_t sBlo = sA + 2 * GMATB;

        #pragma unroll
        for (int kt = 0; kt < 2; ++kt) {
            uint32_t a[2][4];
            #pragma unroll
            for (int mt = 0; mt < 2; ++mt) {
                uint32_t row = wm * 32 + mt * 16 + (lane & 15);
                uint32_t col = kt * 16 + ((lane >> 4) << 3);
                ldsm_x4(a[mt], sA + row * GP + col * 2);
            }
            #pragma unroll
            for (int nt = 0; nt < 8; ++nt) {
                uint32_t bh[2], bl[2];
                uint32_t row = wn * 64 + nt * 8 + (lane & 7);
                uint32_t col = kt * 16 + (lane & 8);
                ldsm_x2(bh, sBhi + row * GP + col * 2);
                ldsm_x2(bl, sBlo + row * GP + col * 2);
                #pragma unroll
                for (int mt = 0; mt < 2; ++mt) {
                    mma_f16(acc[mt][nt], a[mt], bh);
                    mma_f16(acc[mt][nt], a[mt], bl);
                }
            }
        }
        __syncthreads();
        if (it + 2 < 32) {
            gemm_load_stage(sb, st, t, A, Bhi, Blo, m0, n0, (it + 2) * 32);
            CP_COMMIT();
        } else {
            CP_COMMIT();  // keep group counts uniform
        }
    }

    // epilogue
    #pragma unroll
    for (int mt = 0; mt < 2; ++mt)
        #pragma unroll
        for (int nt = 0; nt < 8; ++nt) {
            int r = m0 + wm * 32 + mt * 16 + (lane >> 2);
            int c = n0 + wn * 64 + nt * 8 + (lane & 3) * 2;
            float v0 = acc[mt][nt][0], v1 = acc[mt][nt][1];
            float v2 = acc[mt][nt][2], v3 = acc[mt][nt][3];
            if (MODE == 0) {
                *reinterpret_cast<float2*>(Cf + (size_t)r * DD + c) = make_float2(v0, v1);
                *reinterpret_cast<float2*>(Cf + (size_t)(r + 8) * DD + c) = make_float2(v2, v3);
            } else if (MODE == 1) {
                *reinterpret_cast<uint32_t*>(Ch + (size_t)r * DD + c) = packh(v0, v1);
                *reinterpret_cast<uint32_t*>(Ch + (size_t)(r + 8) * DD + c) = packh(v2, v3);
            } else {
                float h0 = __half2float(__float2half_rn(v0));
                float h1 = __half2float(__float2half_rn(v1));
                float h2 = __half2float(__float2half_rn(v2));
                float h3 = __half2float(__float2half_rn(v3));
                *reinterpret_cast<uint32_t*>(Ch + (size_t)r * DD + c) = packh(h0, h1);
                *reinterpret_cast<uint32_t*>(Ch + (size_t)(r + 8) * DD + c) = packh(h2, h3);
                *reinterpret_cast<uint32_t*>(Cl + (size_t)r * DD + c) =
                    packh(v0 - h0, v1 - h1);
                *reinterpret_cast<uint32_t*>(Cl + (size_t)(r + 8) * DD + c) =
                    packh(v2 - h2, v3 - h3);
            }
        }
}

// ---------------- fused attention on mma.sync --------------------------------
// CTA = (128 q-rows, head, batch); 256 thr, warp = 16 q-rows.
// S = Qhi*K + Qlo*K (Q split, K single fp16); w = exp2(S*C1 + bias*C2) via
// FFMA exp2 (scores bounded, no max subtraction); O += Phi*V + Plo*V.
#define AP 144                    // smem pitch for 64-col fp16 tiles (+pad)
#define AMATB (128 * AP)          // 18432 B
#define A_SQHI 0
#define A_SQLO AMATB
#define A_KV0 (2 * AMATB)         // stage: K, V
#define A_STAGE (2 * AMATB)
#define A_SBIAS (A_KV0 + 2 * A_STAGE)
#define ATT_SMEM (A_SBIAS + 2 * 512)

__device__ __forceinline__ void attn_load_kv(
    uint32_t sb, int st, int t,
    const half_t* __restrict__ k16, const half_t* __restrict__ v16,
    const float* __restrict__ bias, size_t krow0, int hcol, size_t boff)
{
    uint32_t base = sb + A_KV0 + st * A_STAGE;
    #pragma unroll
    for (int i = 0; i < 4; ++i) {
        int ch = t + i * 256;          // 1024 chunks: 128 rows x 8 segs
        int row = ch >> 3, seg = ch & 7;
        size_t ga = (krow0 + row) * DD + hcol + seg * 8;
        uint32_t d = row * AP + seg * 16;
        cp16(base + d, k16 + ga);
        cp16(base + AMATB + d, v16 + ga);
    }
    if (t < 32) cp16(sb + A_SBIAS + st * 512 + t * 16, bias + boff + t * 4);
}

__global__ __launch_bounds__(256) void attn_mma(
    const half_t* __restrict__ qhi, const half_t* __restrict__ qlo,
    const half_t* __restrict__ k16, const half_t* __restrict__ v16,
    const float* __restrict__ bias, half_t* __restrict__ o16)
{
    extern __shared__ char smem[];
    const uint32_t sb = smem_u32(smem);
    const int t = threadIdx.x;
    const int lane = t & 31, wid = t >> 5;
    const int qt = blockIdx.x, h = blockIdx.y, b = blockIdx.z;
    const int hcol = h * DH;
    const size_t qrow0 = (size_t)b * QL + qt * 128;
    const size_t krowb = (size_t)b * KL;
    const float C1 = 0.125f * 1.44269504f;   // scale * log2(e)
    const float C2 = 1.44269504f;

    // load Q tile (hi/lo)
    #pragma unroll
    for (int i = 0; i < 4; ++i) {
        int ch = t + i * 256;
        int row = ch >> 3, seg = ch & 7;
        size_t ga = (qrow0 + row) * DD + hcol + seg * 8;
        uint32_t d = row * AP + seg * 16;
        cp16(sb + A_SQHI + d, qhi + ga);
        cp16(sb + A_SQLO + d, qlo + ga);
    }
    attn_load_kv(sb, 0, t, k16, v16, bias, krowb, hcol, krowb);
    CP_COMMIT();
    attn_load_kv(sb, 1, t, k16, v16, bias, krowb + 128, hcol, krowb + 128);
    CP_COMMIT();

    CP_WAIT1();
    __syncthreads();

    // Q fragments (resident)
    uint32_t qh[4][4], ql[4][4];
    #pragma unroll
    for (int dt = 0; dt < 4; ++dt) {
        uint32_t row = wid * 16 + (lane & 15);
        uint32_t col = dt * 16 + ((lane >> 4) << 3);
        ldsm_x4(qh[dt], sb + A_SQHI + row * AP + col * 2);
        ldsm_x4(ql[dt], sb + A_SQLO + row * AP + col * 2);
    }

    float oacc[8][4] = {};
    float l0 = 0.f, l1 = 0.f;

    for (int it = 0; it < 32; ++it) {
        if (it > 0) {
            if (it < 31) { CP_WAIT1(); } else { CP_WAIT0(); }
            __syncthreads();
        }
        const int st = it & 1;
        const uint32_t sK = sb + A_KV0 + st * A_STAGE;
        const uint32_t sV = sK + AMATB;

        // S = Q K^T  (2-pass: Qhi + Qlo)
        float w[16][4] = {};
        #pragma unroll
        for (int dt = 0; dt < 4; ++dt) {
            #pragma unroll
            for (int nt = 0; nt < 16; ++nt) {
                uint32_t kb[2];
                uint32_t row = nt * 8 + (lane & 7);
                uint32_t col = dt * 16 + (lane & 8);
                ldsm_x2(kb, sK + row * AP + col * 2);
                mma_f16(w[nt], qh[dt], kb);
                mma_f16(w[nt], ql[dt], kb);
            }
        }

        // w = exp(S*scale + bias); accumulate row sums
        #pragma unroll
        for (int nt = 0; nt < 16; ++nt) {
            float2 bv = *reinterpret_cast<const float2*>(
                smem + A_SBIAS + st * 512 + (nt * 8 + (lane & 3) * 2) * 4);
            w[nt][0] = fexp2(fmaf(w[nt][0], C1, bv.x * C2));
            w[nt][1] = fexp2(fmaf(w[nt][1], C1, bv.y * C2));
            w[nt][2] = fexp2(fmaf(w[nt][2], C1, bv.x * C2));
            w[nt][3] = fexp2(fmaf(w[nt][3], C1, bv.y * C2));
            l0 += w[nt][0] + w[nt][1];
            l1 += w[nt][2] + w[nt][3];
        }

        // O += P V  (2-pass: Phi + Plo; P frags from C-layout registers)
        #pragma unroll
        for (int g = 0; g < 8; ++g) {
            float x0 = w[2 * g][0], x1 = w[2 * g][1], x2 = w[2 * g][2], x3 = w[2 * g][3];
            float y0 = w[2 * g + 1][0], y1 = w[2 * g + 1][1];
            float y2 = w[2 * g + 1][2], y3 = w[2 * g + 1][3];
            float hx0 = __half2float(__float2half_rn(x0));
            float hx1 = __half2float(__float2half_rn(x1));
            float hx2 = __half2float(__float2half_rn(x2));
            float hx3 = __half2float(__float2half_rn(x3));
            float hy0 = __half2float(__float2half_rn(y0));
            float hy1 = __half2float(__float2half_rn(y1));
            float hy2 = __half2float(__float2half_rn(y2));
            float hy3 = __half2float(__float2half_rn(y3));
            uint32_t phi[4], plo[4];
            phi[0] = packh(hx0, hx1);  plo[0] = packh(x0 - hx0, x1 - hx1);
            phi[1] = packh(hx2, hx3);  plo[1] = packh(x2 - hx2, x3 - hx3);
            phi[2] = packh(hy0, hy1);  plo[2] = packh(y0 - hy0, y1 - hy1);
            phi[3] = packh(hy2, hy3);  plo[3] = packh(y2 - hy2, y3 - hy3);
            #pragma unroll
            for (int nt = 0; nt < 8; ++nt) {
                uint32_t vb[2];
                uint32_t row = g * 16 + (lane & 15);
                uint32_t col = nt * 8;
                ldsm_x2t(vb, sV + row * AP + col * 2);
                mma_f16(oacc[nt], phi, vb);
                mma_f16(oacc[nt], plo, vb);
            }
        }

        __syncthreads();
        if (it + 2 < 32) {
            attn_load_kv(sb, st, t, k16, v16, bias,
                         krowb + (size_t)(it + 2) * 128, hcol,
                         krowb + (size_t)(it + 2) * 128);
            CP_COMMIT();
        } else {
            CP_COMMIT();
        }
    }

    // reduce row sums across the quad and normalize
    l0 += __shfl_xor_sync(0xffffffffu, l0, 1);
    l0 += __shfl_xor_sync(0xffffffffu, l0, 2);
    l1 += __shfl_xor_sync(0xffffffffu, l1, 1);
    l1 += __shfl_xor_sync(0xffffffffu, l1, 2);
    float inv0 = 1.0f / l0, inv1 = 1.0f / l1;

    size_t r0 = qrow0 + wid * 16 + (lane >> 2);
    size_t r1 = r0 + 8;
    #pragma unroll
    for (int nt = 0; nt < 8; ++nt) {
        int c = hcol + nt * 8 + (lane & 3) * 2;
        *reinterpret_cast<uint32_t*>(o16 + r0 * DD + c) =
            packh(oacc[nt][0] * inv0, oacc[nt][1] * inv0);
        *reinterpret_cast<uint32_t*>(o16 + r1 * DD + c) =
            packh(oacc[nt][2] * inv1, oacc[nt][3] * inv1);
    }
}

// ---------------- conversion kernels ----------------------------------------
__global__ void cvt16_kernel(const float4* __restrict__ x,
                             __half2* __restrict__ y, int n4)
{
    int i = blockIdx.x * blockDim.x + threadIdx.x;
    if (i >= n4) return;
    float4 v = x[i];
    y[2 * i]     = __floats2half2_rn(v.x, v.y);
    y[2 * i + 1] = __floats2half2_rn(v.z, v.w);
}

// 4x W[1024,1024] fp32 row-major -> W^T hi/lo fp16 [N,K], batched over z
__global__ void transpose_split4(const float* __restrict__ W0,
                                 const float* __restrict__ W1,
                                 const float* __restrict__ W2,
                                 const float* __restrict__ W3,
                                 half_t* __restrict__ Thi, half_t* __restrict__ Tlo)
{
    __shared__ float tl[32][33];
    const int tx = threadIdx.x, ty = threadIdx.y;
    const int n0 = blockIdx.x * 32, k0 = blockIdx.y * 32;
    const int z = blockIdx.z;
    const float* W = (z == 0) ? W0 : (z == 1) ? W1 : (z == 2) ? W2 : W3;
    half_t* th = Thi + (size_t)z * DD * DD;
    half_t* tlo = Tlo + (size_t)z * DD * DD;
    #pragma unroll
    for (int i = 0; i < 4; ++i)
        tl[ty + i * 8][tx] = W[(size_t)(k0 + ty + i * 8) * DD + n0 + tx];
    __syncthreads();
    #pragma unroll
    for (int i = 0; i < 4; ++i) {
        float v = tl[tx][ty + i * 8];  // = W[k0+tx][n0+ty+i*8]
        half_t hv = __float2half_rn(v);
        size_t idx = (size_t)(n0 + ty + i * 8) * DD + k0 + tx;
        th[idx] = hv;
        tlo[idx] = __float2half_rn(v - __half2float(hv));
    }
}

// ---------------- host launch -------------------------------------------------
extern "C" void kernel_launch(void* const* d_in, const int* in_sizes, int n_in,
                              void* d_out, int out_size)
{
    const float* query  = (const float*)d_in[0];
    const float* memory = (const float*)d_in[1];
    const float* bias   = (const float*)d_in[2];
    const float* W0 = (const float*)d_in[3];
    const float* W1 = (const float*)d_in[4];
    const float* W2 = (const float*)d_in[5];
    const float* W3 = (const float*)d_in[6];
    float* out = (float*)d_out;

    half_t *iq16, *im16, *wth, *wtl, *qh, *qlp, *k16, *v16, *a16;
    cudaGetSymbolAddress((void**)&iq16, gi_q16);
    cudaGetSymbolAddress((void**)&im16, gi_m16);
    cudaGetSymbolAddress((void**)&wth, g_wthi);
    cudaGetSymbolAddress((void**)&wtl, g_wtlo);
    cudaGetSymbolAddress((void**)&qh, g_qhi);
    cudaGetSymbolAddress((void**)&qlp, g_qlo);
    cudaGetSymbolAddress((void**)&k16, g_k16);
    cudaGetSymbolAddress((void**)&v16, g_v16);
    cudaGetSymbolAddress((void**)&a16, g_a16);

    static int attr_set = 0;
    if (!attr_set) {
        cudaFuncSetAttribute(gemm_mma<0>, cudaFuncAttributeMaxDynamicSharedMemorySize,
                             GEMM_SMEM);
        cudaFuncSetAttribute(gemm_mma<1>, cudaFuncAttributeMaxDynamicSharedMemorySize,
                             GEMM_SMEM);
        cudaFuncSetAttribute(gemm_mma<2>, cudaFuncAttributeMaxDynamicSharedMemorySize,
                             GEMM_SMEM);
        cudaFuncSetAttribute(attn_mma, cudaFuncAttributeMaxDynamicSharedMemorySize,
                             ATT_SMEM);
        attr_set = 1;
    }

    // convert inputs to fp16
    {
        int n4 = (BB * QL * DD) / 4;
        cvt16_kernel<<<n4 / 256, 256>>>((const float4*)query, (__half2*)iq16, n4);
    }
    {
        int n4 = (BB * KL * DD) / 4;
        cvt16_kernel<<<n4 / 256, 256>>>((const float4*)memory, (__half2*)im16, n4);
    }
    // all 4 weight transpose+splits in one launch
    {
        dim3 thr(32, 8), grid(DD / 32, DD / 32, 4);
        transpose_split4<<<grid, thr>>>(W0, W1, W2, W3, wth, wtl);
    }

    // projections
    {
        dim3 grid(DD / 128, (BB * QL) / 128);
        gemm_mma<2><<<grid, 256, GEMM_SMEM>>>(iq16, wth, wtl, nullptr, qh, qlp);
    }
    {
        dim3 grid(DD / 128, (BB * KL) / 128);
        gemm_mma<1><<<grid, 256, GEMM_SMEM>>>(im16, wth + (size_t)DD * DD,
                                              wtl + (size_t)DD * DD, nullptr, k16, nullptr);
        gemm_mma<1><<<grid, 256, GEMM_SMEM>>>(im16, wth + 2 * (size_t)DD * DD,
                                              wtl + 2 * (size_t)DD * DD, nullptr, v16, nullptr);
    }
    // attention
    {
        dim3 grid(QL / 128, NH, BB);
        attn_mma<<<grid, 256, ATT_SMEM>>>(qh, qlp, k16, v16, bias, a16);
    }
    // O projection -> fp32 out
    {
        dim3 grid(DD / 128, (BB * QL) / 128);
        gemm_mma<0><<<grid, 256, GEMM_SMEM>>>(a16, wth + 3 * (size_t)DD * DD,
                                              wtl + 3 * (size_t)DD * DD, out, nullptr,
                                              nullptr);
    }
}

// round 5
// speedup vs baseline: 5.3361x; 1.0583x over previous
#include <cuda_runtime.h>
#include <cuda_fp16.h>
#include <math.h>
#include <stdint.h>

// Problem constants:
//   query [4,512,1024], memory [4,4096,1024], bias [4,4096]
//   Wq,Wk,Wv,Wo [1024,1024] -> out [4,512,1024] fp32
#define BB 4
#define QL 512
#define KL 4096
#define DD 1024
#define NH 16
#define DH 64

typedef __half half_t;

// ---------------- scratch (static device arrays) ---------------------------
__device__ __align__(128) half_t gi_q16[(size_t)BB * QL * DD];   // query fp16
__device__ __align__(128) half_t gi_m16[(size_t)BB * KL * DD];   // memory fp16
__device__ __align__(128) half_t g_wthi[4 * (size_t)DD * DD];    // W^T hi fp16
__device__ __align__(128) half_t g_wtlo[4 * (size_t)DD * DD];    // W^T lo fp16
__device__ __align__(128) half_t g_qhi[(size_t)BB * QL * DD];    // Q hi/lo
__device__ __align__(128) half_t g_qlo[(size_t)BB * QL * DD];
__device__ __align__(128) half_t g_k16[(size_t)BB * KL * DD];    // K single fp16
__device__ __align__(128) half_t g_v16[(size_t)BB * KL * DD];    // V single fp16
__device__ __align__(128) half_t g_a16[(size_t)BB * QL * DD];    // attn out fp16

// ---------------- PTX helpers ------------------------------------------------
__device__ __forceinline__ uint32_t smem_u32(const void* p) {
    uint32_t a;
    asm("{ .reg .u64 t; cvta.to.shared.u64 t, %1; cvt.u32.u64 %0, t; }" : "=r"(a) : "l"(p));
    return a;
}
__device__ __forceinline__ void cp16(uint32_t dst, const void* src) {
    asm volatile("cp.async.cg.shared.global [%0], [%1], 16;" :: "r"(dst), "l"(src));
}
#define CP_COMMIT() asm volatile("cp.async.commit_group;" ::: "memory")
#define CP_WAIT1()  asm volatile("cp.async.wait_group 1;" ::: "memory")
#define CP_WAIT0()  asm volatile("cp.async.wait_group 0;" ::: "memory")

__device__ __forceinline__ void ldsm_x4(uint32_t (&r)[4], uint32_t addr) {
    asm volatile("ldmatrix.sync.aligned.m8n8.x4.shared.b16 {%0,%1,%2,%3}, [%4];"
        : "=r"(r[0]), "=r"(r[1]), "=r"(r[2]), "=r"(r[3]) : "r"(addr));
}
__device__ __forceinline__ void ldsm_x4t(uint32_t (&r)[4], uint32_t addr) {
    asm volatile("ldmatrix.sync.aligned.m8n8.x4.trans.shared.b16 {%0,%1,%2,%3}, [%4];"
        : "=r"(r[0]), "=r"(r[1]), "=r"(r[2]), "=r"(r[3]) : "r"(addr));
}
__device__ __forceinline__ void mma_f16(float (&d)[4], const uint32_t (&a)[4],
                                        uint32_t b0, uint32_t b1) {
    asm volatile(
        "mma.sync.aligned.m16n8k16.row.col.f32.f16.f16.f32 "
        "{%0,%1,%2,%3}, {%4,%5,%6,%7}, {%8,%9}, {%0,%1,%2,%3};"
        : "+f"(d[0]), "+f"(d[1]), "+f"(d[2]), "+f"(d[3])
        : "r"(a[0]), "r"(a[1]), "r"(a[2]), "r"(a[3]), "r"(b0), "r"(b1));
}
__device__ __forceinline__ uint32_t packh(float a, float b) {
    __half2 t = __floats2half2_rn(a, b);
    return *reinterpret_cast<uint32_t*>(&t);
}

// FFMA-only exp2 (floor + deg-6 poly, rel err ~1e-5); avoids MUFU.
__device__ __forceinline__ float fexp2(float x) {
    x = fminf(fmaxf(x, -126.f), 126.f);
    float fl = floorf(x);
    float f = x - fl;
    float p = 1.54035304e-4f;
    p = fmaf(p, f, 1.33335581e-3f);
    p = fmaf(p, f, 9.61812911e-3f);
    p = fmaf(p, f, 5.55041087e-2f);
    p = fmaf(p, f, 2.40226507e-1f);
    p = fmaf(p, f, 6.93147181e-1f);
    p = fmaf(p, f, 1.0f);
    return p * __int_as_float(((int)fl + 127) << 23);
}

// ---------------- split-fp16 MMA GEMM ---------------------------------------
// C[M,1024] = A[M,1024] @ W[1024,1024]; A single fp16 [M,K], W^T split hi/lo
// fp16 [N,K]. 2-pass: A*Whi + A*Wlo. CTA = 128x128 tile, BK=32.
// 128 threads (4 warps, 2x2 grid of 64x64 warp tiles), cp.async 2-stage.
// MODE 0: fp32 out. MODE 1: single fp16 out. MODE 2: hi/lo fp16 out.
#define GP 80            // smem row pitch bytes (32 fp16 + pad), conflict free
#define GMATB (128 * GP) // 10240 B per matrix tile
#define GSTAGE (3 * GMATB)
#define GEMM_SMEM (2 * GSTAGE)

__device__ __forceinline__ void gemm_load_stage(
    uint32_t sb, int st, int t,
    const half_t* __restrict__ A,
    const half_t* __restrict__ Bhi, const half_t* __restrict__ Blo,
    int m0, int n0, int k0)
{
    uint32_t base = sb + st * GSTAGE;
    #pragma unroll
    for (int i = 0; i < 4; ++i) {
        int ch = t + i * 128;          // 512 chunks: 128 rows x 4 (16B) segs
        int row = ch >> 2, seg = ch & 3;
        uint32_t d = row * GP + seg * 16;
        cp16(base + d, A + (size_t)(m0 + row) * DD + k0 + seg * 8);
        size_t gb = (size_t)(n0 + row) * DD + k0 + seg * 8;
        cp16(base + GMATB + d, Bhi + gb);
        cp16(base + 2 * GMATB + d, Blo + gb);
    }
}

template <int MODE>
__global__ __launch_bounds__(128, 2) void gemm_mma(
    const half_t* __restrict__ A,
    const half_t* __restrict__ Bhi, const half_t* __restrict__ Blo,
    float* __restrict__ Cf, half_t* __restrict__ Ch, half_t* __restrict__ Cl)
{
    extern __shared__ char smem[];
    const uint32_t sb = smem_u32(smem);
    const int t = threadIdx.x;
    const int lane = t & 31, wid = t >> 5;
    const int wm = wid >> 1, wn = wid & 1;   // 2 x 2 warp grid, 64x64 tiles
    const int n0 = blockIdx.x * 128, m0 = blockIdx.y * 128;

    float acc[4][8][4] = {};

    gemm_load_stage(sb, 0, t, A, Bhi, Blo, m0, n0, 0);
    CP_COMMIT();
    gemm_load_stage(sb, 1, t, A, Bhi, Blo, m0, n0, 32);
    CP_COMMIT();

    for (int it = 0; it < 32; ++it) {
        if (it < 31) { CP_WAIT1(); } else { CP_WAIT0(); }
        __syncthreads();

        const int st = it & 1;
        const uint32_t sA   = sb + st * GSTAGE;
        const uint32_t sBhi = sA + GMATB;
        const uint32_t sBlo = sA + 2 * GMATB;

        #pragma unroll
        for (int kt = 0; kt < 2; ++kt) {
            uint32_t a[4][4];
            #pragma unroll
            for (int mt = 0; mt < 4; ++mt) {
                uint32_t row = wm * 64 + mt * 16 + (lane & 15);
                uint32_t col = kt * 16 + ((lane >> 4) << 3);
                ldsm_x4(a[mt], sA + row * GP + col * 2);
            }
            #pragma unroll
            for (int nb = 0; nb < 4; ++nb) {
                uint32_t bh[4], bl[4];
                uint32_t row = wn * 64 + nb * 16 + ((lane >> 4) << 3) + (lane & 7);
                uint32_t col = kt * 16 + (lane & 8);
                ldsm_x4(bh, sBhi + row * GP + col * 2);
                ldsm_x4(bl, sBlo + row * GP + col * 2);
                #pragma unroll
                for (int mt = 0; mt < 4; ++mt) {
                    mma_f16(acc[mt][2 * nb],     a[mt], bh[0], bh[1]);
                    mma_f16(acc[mt][2 * nb],     a[mt], bl[0], bl[1]);
                    mma_f16(acc[mt][2 * nb + 1], a[mt], bh[2], bh[3]);
                    mma_f16(acc[mt][2 * nb + 1], a[mt], bl[2], bl[3]);
                }
            }
        }
        __syncthreads();
        if (it + 2 < 32) {
            gemm_load_stage(sb, st, t, A, Bhi, Blo, m0, n0, (it + 2) * 32);
            CP_COMMIT();
        } else {
            CP_COMMIT();  // keep group counts uniform
        }
    }

    // epilogue
    #pragma unroll
    for (int mt = 0; mt < 4; ++mt)
        #pragma unroll
        for (int nt = 0; nt < 8; ++nt) {
            int r = m0 + wm * 64 + mt * 16 + (lane >> 2);
            int c = n0 + wn * 64 + nt * 8 + (lane & 3) * 2;
            float v0 = acc[mt][nt][0], v1 = acc[mt][nt][1];
            float v2 = acc[mt][nt][2], v3 = acc[mt][nt][3];
            if (MODE == 0) {
                *reinterpret_cast<float2*>(Cf + (size_t)r * DD + c) = make_float2(v0, v1);
                *reinterpret_cast<float2*>(Cf + (size_t)(r + 8) * DD + c) = make_float2(v2, v3);
            } else if (MODE == 1) {
                *reinterpret_cast<uint32_t*>(Ch + (size_t)r * DD + c) = packh(v0, v1);
                *reinterpret_cast<uint32_t*>(Ch + (size_t)(r + 8) * DD + c) = packh(v2, v3);
            } else {
                float h0 = __half2float(__float2half_rn(v0));
                float h1 = __half2float(__float2half_rn(v1));
                float h2 = __half2float(__float2half_rn(v2));
                float h3 = __half2float(__float2half_rn(v3));
                *reinterpret_cast<uint32_t*>(Ch + (size_t)r * DD + c) = packh(h0, h1);
                *reinterpret_cast<uint32_t*>(Ch + (size_t)(r + 8) * DD + c) = packh(h2, h3);
                *reinterpret_cast<uint32_t*>(Cl + (size_t)r * DD + c) =
                    packh(v0 - h0, v1 - h1);
                *reinterpret_cast<uint32_t*>(Cl + (size_t)(r + 8) * DD + c) =
                    packh(v2 - h2, v3 - h3);
            }
        }
}

// ---------------- fused attention on mma.sync --------------------------------
// CTA = (128 q-rows, head, batch); 256 thr, warp = 16 q-rows.
// S = Qhi*K + Qlo*K; w = exp2(S*C1 + bias*C2) via FFMA exp2 (scores bounded,
// no max subtraction); O += Phi*V + Plo*V. K/V frags via paired ldsm_x4.
#define AP 144                    // smem pitch for 64-col fp16 tiles (+pad)
#define AMATB (128 * AP)          // 18432 B
#define A_SQHI 0
#define A_SQLO AMATB
#define A_KV0 (2 * AMATB)         // stage: K, V
#define A_STAGE (2 * AMATB)
#define A_SBIAS (A_KV0 + 2 * A_STAGE)
#define ATT_SMEM (A_SBIAS + 2 * 512)

__device__ __forceinline__ void attn_load_kv(
    uint32_t sb, int st, int t,
    const half_t* __restrict__ k16, const half_t* __restrict__ v16,
    const float* __restrict__ bias, size_t krow0, int hcol, size_t boff)
{
    uint32_t base = sb + A_KV0 + st * A_STAGE;
    #pragma unroll
    for (int i = 0; i < 4; ++i) {
        int ch = t + i * 256;          // 1024 chunks: 128 rows x 8 segs
        int row = ch >> 3, seg = ch & 7;
        size_t ga = (krow0 + row) * DD + hcol + seg * 8;
        uint32_t d = row * AP + seg * 16;
        cp16(base + d, k16 + ga);
        cp16(base + AMATB + d, v16 + ga);
    }
    if (t < 32) cp16(sb + A_SBIAS + st * 512 + t * 16, bias + boff + t * 4);
}

__global__ __launch_bounds__(256) void attn_mma(
    const half_t* __restrict__ qhi, const half_t* __restrict__ qlo,
    const half_t* __restrict__ k16, const half_t* __restrict__ v16,
    const float* __restrict__ bias, half_t* __restrict__ o16)
{
    extern __shared__ char smem[];
    const uint32_t sb = smem_u32(smem);
    const int t = threadIdx.x;
    const int lane = t & 31, wid = t >> 5;
    const int qt = blockIdx.x, h = blockIdx.y, b = blockIdx.z;
    const int hcol = h * DH;
    const size_t qrow0 = (size_t)b * QL + qt * 128;
    const size_t krowb = (size_t)b * KL;
    const float C1 = 0.125f * 1.44269504f;   // scale * log2(e)
    const float C2 = 1.44269504f;

    // load Q tile (hi/lo)
    #pragma unroll
    for (int i = 0; i < 4; ++i) {
        int ch = t + i * 256;
        int row = ch >> 3, seg = ch & 7;
        size_t ga = (qrow0 + row) * DD + hcol + seg * 8;
        uint32_t d = row * AP + seg * 16;
        cp16(sb + A_SQHI + d, qhi + ga);
        cp16(sb + A_SQLO + d, qlo + ga);
    }
    attn_load_kv(sb, 0, t, k16, v16, bias, krowb, hcol, krowb);
    CP_COMMIT();
    attn_load_kv(sb, 1, t, k16, v16, bias, krowb + 128, hcol, krowb + 128);
    CP_COMMIT();

    CP_WAIT1();
    __syncthreads();

    // Q fragments (resident)
    uint32_t qh[4][4], ql[4][4];
    #pragma unroll
    for (int dt = 0; dt < 4; ++dt) {
        uint32_t row = wid * 16 + (lane & 15);
        uint32_t col = dt * 16 + ((lane >> 4) << 3);
        ldsm_x4(qh[dt], sb + A_SQHI + row * AP + col * 2);
        ldsm_x4(ql[dt], sb + A_SQLO + row * AP + col * 2);
    }

    float oacc[8][4] = {};
    float l0 = 0.f, l1 = 0.f;

    for (int it = 0; it < 32; ++it) {
        if (it > 0) {
            if (it < 31) { CP_WAIT1(); } else { CP_WAIT0(); }
            __syncthreads();
        }
        const int st = it & 1;
        const uint32_t sK = sb + A_KV0 + st * A_STAGE;
        const uint32_t sV = sK + AMATB;

        // S = Q K^T  (2-pass: Qhi + Qlo); K frags via paired ldsm_x4
        float w[16][4] = {};
        #pragma unroll
        for (int dt = 0; dt < 4; ++dt) {
            #pragma unroll
            for (int np = 0; np < 8; ++np) {
                uint32_t kb[4];
                uint32_t row = np * 16 + ((lane >> 4) << 3) + (lane & 7);
                uint32_t col = dt * 16 + (lane & 8);
                ldsm_x4(kb, sK + row * AP + col * 2);
                mma_f16(w[2 * np],     qh[dt], kb[0], kb[1]);
                mma_f16(w[2 * np],     ql[dt], kb[0], kb[1]);
                mma_f16(w[2 * np + 1], qh[dt], kb[2], kb[3]);
                mma_f16(w[2 * np + 1], ql[dt], kb[2], kb[3]);
            }
        }

        // w = exp(S*scale + bias); accumulate row sums
        #pragma unroll
        for (int nt = 0; nt < 16; ++nt) {
            float2 bv = *reinterpret_cast<const float2*>(
                smem + A_SBIAS + st * 512 + (nt * 8 + (lane & 3) * 2) * 4);
            w[nt][0] = fexp2(fmaf(w[nt][0], C1, bv.x * C2));
            w[nt][1] = fexp2(fmaf(w[nt][1], C1, bv.y * C2));
            w[nt][2] = fexp2(fmaf(w[nt][2], C1, bv.x * C2));
            w[nt][3] = fexp2(fmaf(w[nt][3], C1, bv.y * C2));
            l0 += w[nt][0] + w[nt][1];
            l1 += w[nt][2] + w[nt][3];
        }

        // O += P V  (2-pass: Phi + Plo; V frags via paired ldsm_x4.trans)
        #pragma unroll
        for (int g = 0; g < 8; ++g) {
            float x0 = w[2 * g][0], x1 = w[2 * g][1], x2 = w[2 * g][2], x3 = w[2 * g][3];
            float y0 = w[2 * g + 1][0], y1 = w[2 * g + 1][1];
            float y2 = w[2 * g + 1][2], y3 = w[2 * g + 1][3];
            float hx0 = __half2float(__float2half_rn(x0));
            float hx1 = __half2float(__float2half_rn(x1));
            float hx2 = __half2float(__float2half_rn(x2));
            float hx3 = __half2float(__float2half_rn(x3));
            float hy0 = __half2float(__float2half_rn(y0));
            float hy1 = __half2float(__float2half_rn(y1));
            float hy2 = __half2float(__float2half_rn(y2));
            float hy3 = __half2float(__float2half_rn(y3));
            uint32_t phi[4], plo[4];
            phi[0] = packh(hx0, hx1);  plo[0] = packh(x0 - hx0, x1 - hx1);
            phi[1] = packh(hx2, hx3);  plo[1] = packh(x2 - hx2, x3 - hx3);
            phi[2] = packh(hy0, hy1);  plo[2] = packh(y0 - hy0, y1 - hy1);
            phi[3] = packh(hy2, hy3);  plo[3] = packh(y2 - hy2, y3 - hy3);
            #pragma unroll
            for (int np = 0; np < 4; ++np) {
                uint32_t vb[4];
                uint32_t row = g * 16 + (lane & 15);
                uint32_t col = np * 16 + ((lane >> 4) << 3);
                ldsm_x4t(vb, sV + row * AP + col * 2);
                mma_f16(oacc[2 * np],     phi, vb[0], vb[1]);
                mma_f16(oacc[2 * np],     plo, vb[0], vb[1]);
                mma_f16(oacc[2 * np + 1], phi, vb[2], vb[3]);
                mma_f16(oacc[2 * np + 1], plo, vb[2], vb[3]);
            }
        }

        __syncthreads();
        if (it + 2 < 32) {
            attn_load_kv(sb, st, t, k16, v16, bias,
                         krowb + (size_t)(it + 2) * 128, hcol,
                         krowb + (size_t)(it + 2) * 128);
            CP_COMMIT();
        } else {
            CP_COMMIT();
        }
    }

    // reduce row sums across the quad and normalize
    l0 += __shfl_xor_sync(0xffffffffu, l0, 1);
    l0 += __shfl_xor_sync(0xffffffffu, l0, 2);
    l1 += __shfl_xor_sync(0xffffffffu, l1, 1);
    l1 += __shfl_xor_sync(0xffffffffu, l1, 2);
    float inv0 = 1.0f / l0, inv1 = 1.0f / l1;

    size_t r0 = qrow0 + wid * 16 + (lane >> 2);
    size_t r1 = r0 + 8;
    #pragma unroll
    for (int nt = 0; nt < 8; ++nt) {
        int c = hcol + nt * 8 + (lane & 3) * 2;
        *reinterpret_cast<uint32_t*>(o16 + r0 * DD + c) =
            packh(oacc[nt][0] * inv0, oacc[nt][1] * inv0);
        *reinterpret_cast<uint32_t*>(o16 + r1 * DD + c) =
            packh(oacc[nt][2] * inv1, oacc[nt][3] * inv1);
    }
}

// ---------------- conversion kernels ----------------------------------------
__global__ void cvt16_kernel(const float4* __restrict__ x,
                             __half2* __restrict__ y, int n4)
{
    int i = blockIdx.x * blockDim.x + threadIdx.x;
    if (i >= n4) return;
    float4 v = x[i];
    y[2 * i]     = __floats2half2_rn(v.x, v.y);
    y[2 * i + 1] = __floats2half2_rn(v.z, v.w);
}

// 4x W[1024,1024] fp32 row-major -> W^T hi/lo fp16 [N,K], batched over z
__global__ void transpose_split4(const float* __restrict__ W0,
                                 const float* __restrict__ W1,
                                 const float* __restrict__ W2,
                                 const float* __restrict__ W3,
                                 half_t* __restrict__ Thi, half_t* __restrict__ Tlo)
{
    __shared__ float tl[32][33];
    const int tx = threadIdx.x, ty = threadIdx.y;
    const int n0 = blockIdx.x * 32, k0 = blockIdx.y * 32;
    const int z = blockIdx.z;
    const float* W = (z == 0) ? W0 : (z == 1) ? W1 : (z == 2) ? W2 : W3;
    half_t* th = Thi + (size_t)z * DD * DD;
    half_t* tlo = Tlo + (size_t)z * DD * DD;
    #pragma unroll
    for (int i = 0; i < 4; ++i)
        tl[ty + i * 8][tx] = W[(size_t)(k0 + ty + i * 8) * DD + n0 + tx];
    __syncthreads();
    #pragma unroll
    for (int i = 0; i < 4; ++i) {
        float v = tl[tx][ty + i * 8];  // = W[k0+tx][n0+ty+i*8]
        half_t hv = __float2half_rn(v);
        size_t idx = (size_t)(n0 + ty + i * 8) * DD + k0 + tx;
        th[idx] = hv;
        tlo[idx] = __float2half_rn(v - __half2float(hv));
    }
}

// ---------------- host launch -------------------------------------------------
extern "C" void kernel_launch(void* const* d_in, const int* in_sizes, int n_in,
                              void* d_out, int out_size)
{
    const float* query  = (const float*)d_in[0];
    const float* memory = (const float*)d_in[1];
    const float* bias   = (const float*)d_in[2];
    const float* W0 = (const float*)d_in[3];
    const float* W1 = (const float*)d_in[4];
    const float* W2 = (const float*)d_in[5];
    const float* W3 = (const float*)d_in[6];
    float* out = (float*)d_out;

    half_t *iq16, *im16, *wth, *wtl, *qh, *qlp, *k16, *v16, *a16;
    cudaGetSymbolAddress((void**)&iq16, gi_q16);
    cudaGetSymbolAddress((void**)&im16, gi_m16);
    cudaGetSymbolAddress((void**)&wth, g_wthi);
    cudaGetSymbolAddress((void**)&wtl, g_wtlo);
    cudaGetSymbolAddress((void**)&qh, g_qhi);
    cudaGetSymbolAddress((void**)&qlp, g_qlo);
    cudaGetSymbolAddress((void**)&k16, g_k16);
    cudaGetSymbolAddress((void**)&v16, g_v16);
    cudaGetSymbolAddress((void**)&a16, g_a16);

    static int attr_set = 0;
    if (!attr_set) {
        cudaFuncSetAttribute(gemm_mma<0>, cudaFuncAttributeMaxDynamicSharedMemorySize,
                             GEMM_SMEM);
        cudaFuncSetAttribute(gemm_mma<1>, cudaFuncAttributeMaxDynamicSharedMemorySize,
                             GEMM_SMEM);
        cudaFuncSetAttribute(gemm_mma<2>, cudaFuncAttributeMaxDynamicSharedMemorySize,
                             GEMM_SMEM);
        cudaFuncSetAttribute(attn_mma, cudaFuncAttributeMaxDynamicSharedMemorySize,
                             ATT_SMEM);
        attr_set = 1;
    }

    // convert inputs to fp16
    {
        int n4 = (BB * QL * DD) / 4;
        cvt16_kernel<<<n4 / 256, 256>>>((const float4*)query, (__half2*)iq16, n4);
    }
    {
        int n4 = (BB * KL * DD) / 4;
        cvt16_kernel<<<n4 / 256, 256>>>((const float4*)memory, (__half2*)im16, n4);
    }
    // all 4 weight transpose+splits in one launch
    {
        dim3 thr(32, 8), grid(DD / 32, DD / 32, 4);
        transpose_split4<<<grid, thr>>>(W0, W1, W2, W3, wth, wtl);
    }

    // projections
    {
        dim3 grid(DD / 128, (BB * QL) / 128);
        gemm_mma<2><<<grid, 128, GEMM_SMEM>>>(iq16, wth, wtl, nullptr, qh, qlp);
    }
    {
        dim3 grid(DD / 128, (BB * KL) / 128);
        gemm_mma<1><<<grid, 128, GEMM_SMEM>>>(im16, wth + (size_t)DD * DD,
                                              wtl + (size_t)DD * DD, nullptr, k16, nullptr);
        gemm_mma<1><<<grid, 128, GEMM_SMEM>>>(im16, wth + 2 * (size_t)DD * DD,
                                              wtl + 2 * (size_t)DD * DD, nullptr, v16, nullptr);
    }
    // attention
    {
        dim3 grid(QL / 128, NH, BB);
        attn_mma<<<grid, 256, ATT_SMEM>>>(qh, qlp, k16, v16, bias, a16);
    }
    // O projection -> fp32 out
    {
        dim3 grid(DD / 128, (BB * QL) / 128);
        gemm_mma<0><<<grid, 128, GEMM_SMEM>>>(a16, wth + 3 * (size_t)DD * DD,
                                              wtl + 3 * (size_t)DD * DD, out, nullptr,
                                              nullptr);
    }
}

// round 6
// speedup vs baseline: 7.7870x; 1.4593x over previous
#include <cuda_runtime.h>
#include <cuda_fp16.h>
#include <math.h>
#include <stdint.h>

// Problem constants:
//   query [4,512,1024], memory [4,4096,1024], bias [4,4096]
//   Wq,Wk,Wv,Wo [1024,1024] -> out [4,512,1024] fp32
#define BB 4
#define QL 512
#define KL 4096
#define DD 1024
#define NH 16
#define DH 64

typedef __half half_t;

// ---------------- scratch (static device arrays) ---------------------------
__device__ __align__(128) half_t gi_q16[(size_t)BB * QL * DD];   // query fp16
__device__ __align__(128) half_t gi_m16[(size_t)BB * KL * DD];   // memory fp16
__device__ __align__(128) half_t g_wthi[4 * (size_t)DD * DD];    // W^T hi fp16
__device__ __align__(128) half_t g_wtlo[4 * (size_t)DD * DD];    // W^T lo fp16
__device__ __align__(128) half_t g_qhi[(size_t)BB * QL * DD];    // Q hi/lo
__device__ __align__(128) half_t g_qlo[(size_t)BB * QL * DD];
__device__ __align__(128) half_t g_k16[(size_t)BB * KL * DD];    // K single fp16
__device__ __align__(128) half_t g_v16[(size_t)BB * KL * DD];    // V single fp16
__device__ __align__(128) half_t g_a16[(size_t)BB * QL * DD];    // attn out fp16

// ---------------- PTX helpers ------------------------------------------------
__device__ __forceinline__ uint32_t smem_u32(const void* p) {
    uint32_t a;
    asm("{ .reg .u64 t; cvta.to.shared.u64 t, %1; cvt.u32.u64 %0, t; }" : "=r"(a) : "l"(p));
    return a;
}
__device__ __forceinline__ void cp16(uint32_t dst, const void* src) {
    asm volatile("cp.async.cg.shared.global [%0], [%1], 16;" :: "r"(dst), "l"(src));
}
#define CP_COMMIT() asm volatile("cp.async.commit_group;" ::: "memory")
#define CP_WAIT1()  asm volatile("cp.async.wait_group 1;" ::: "memory")
#define CP_WAIT0()  asm volatile("cp.async.wait_group 0;" ::: "memory")

__device__ __forceinline__ void ldsm_x4(uint32_t (&r)[4], uint32_t addr) {
    asm volatile("ldmatrix.sync.aligned.m8n8.x4.shared.b16 {%0,%1,%2,%3}, [%4];"
        : "=r"(r[0]), "=r"(r[1]), "=r"(r[2]), "=r"(r[3]) : "r"(addr));
}
__device__ __forceinline__ void ldsm_x4t(uint32_t (&r)[4], uint32_t addr) {
    asm volatile("ldmatrix.sync.aligned.m8n8.x4.trans.shared.b16 {%0,%1,%2,%3}, [%4];"
        : "=r"(r[0]), "=r"(r[1]), "=r"(r[2]), "=r"(r[3]) : "r"(addr));
}
__device__ __forceinline__ void mma_f16(float (&d)[4], const uint32_t (&a)[4],
                                        uint32_t b0, uint32_t b1) {
    asm volatile(
        "mma.sync.aligned.m16n8k16.row.col.f32.f16.f16.f32 "
        "{%0,%1,%2,%3}, {%4,%5,%6,%7}, {%8,%9}, {%0,%1,%2,%3};"
        : "+f"(d[0]), "+f"(d[1]), "+f"(d[2]), "+f"(d[3])
        : "r"(a[0]), "r"(a[1]), "r"(a[2]), "r"(a[3]), "r"(b0), "r"(b1));
}
__device__ __forceinline__ uint32_t packh(float a, float b) {
    __half2 t = __floats2half2_rn(a, b);
    return *reinterpret_cast<uint32_t*>(&t);
}

// FFMA-only exp2 (floor + deg-6 poly, rel err ~1e-5); avoids MUFU.
__device__ __forceinline__ float fexp2(float x) {
    x = fminf(fmaxf(x, -126.f), 126.f);
    float fl = floorf(x);
    float f = x - fl;
    float p = 1.54035304e-4f;
    p = fmaf(p, f, 1.33335581e-3f);
    p = fmaf(p, f, 9.61812911e-3f);
    p = fmaf(p, f, 5.55041087e-2f);
    p = fmaf(p, f, 2.40226507e-1f);
    p = fmaf(p, f, 6.93147181e-1f);
    p = fmaf(p, f, 1.0f);
    return p * __int_as_float(((int)fl + 127) << 23);
}

// ---------------- split-fp16 MMA GEMM ---------------------------------------
// C[M,1024] = A[M,1024] @ W[1024,1024]; A single fp16 [M,K], W^T fp16 [N,K]
// (optionally split hi/lo). PASSES=2: A*Whi + A*Wlo. PASSES=1: A*Whi only.
// CTA = 128x128 tile, BK=32, 128 threads (4 warps, 2x2 of 64x64 warp tiles).
// MODE 0: fp32 out. MODE 1: single fp16 out. MODE 2: hi/lo fp16 out.
#define GP 80            // smem row pitch bytes (32 fp16 + pad), conflict free
#define GMATB (128 * GP) // 10240 B per matrix tile
#define GSTAGE (3 * GMATB)
#define GEMM_SMEM (2 * GSTAGE)

template <int PASSES>
__device__ __forceinline__ void gemm_load_stage(
    uint32_t sb, int st, int t,
    const half_t* __restrict__ A,
    const half_t* __restrict__ Bhi, const half_t* __restrict__ Blo,
    int m0, int n0, int k0)
{
    uint32_t base = sb + st * GSTAGE;
    #pragma unroll
    for (int i = 0; i < 4; ++i) {
        int ch = t + i * 128;          // 512 chunks: 128 rows x 4 (16B) segs
        int row = ch >> 2, seg = ch & 3;
        uint32_t d = row * GP + seg * 16;
        cp16(base + d, A + (size_t)(m0 + row) * DD + k0 + seg * 8);
        size_t gb = (size_t)(n0 + row) * DD + k0 + seg * 8;
        cp16(base + GMATB + d, Bhi + gb);
        if (PASSES == 2) cp16(base + 2 * GMATB + d, Blo + gb);
    }
}

template <int MODE, int PASSES>
__global__ __launch_bounds__(128, 2) void gemm_mma(
    const half_t* __restrict__ A,
    const half_t* __restrict__ Bhi, const half_t* __restrict__ Blo,
    float* __restrict__ Cf, half_t* __restrict__ Ch, half_t* __restrict__ Cl)
{
    extern __shared__ char smem[];
    const uint32_t sb = smem_u32(smem);
    const int t = threadIdx.x;
    const int lane = t & 31, wid = t >> 5;
    const int wm = wid >> 1, wn = wid & 1;   // 2 x 2 warp grid, 64x64 tiles
    const int n0 = blockIdx.x * 128, m0 = blockIdx.y * 128;

    float acc[4][8][4] = {};

    gemm_load_stage<PASSES>(sb, 0, t, A, Bhi, Blo, m0, n0, 0);
    CP_COMMIT();
    gemm_load_stage<PASSES>(sb, 1, t, A, Bhi, Blo, m0, n0, 32);
    CP_COMMIT();

    for (int it = 0; it < 32; ++it) {
        if (it < 31) { CP_WAIT1(); } else { CP_WAIT0(); }
        __syncthreads();

        const int st = it & 1;
        const uint32_t sA   = sb + st * GSTAGE;
        const uint32_t sBhi = sA + GMATB;
        const uint32_t sBlo = sA + 2 * GMATB;

        #pragma unroll
        for (int kt = 0; kt < 2; ++kt) {
            uint32_t a[4][4];
            #pragma unroll
            for (int mt = 0; mt < 4; ++mt) {
                uint32_t row = wm * 64 + mt * 16 + (lane & 15);
                uint32_t col = kt * 16 + ((lane >> 4) << 3);
                ldsm_x4(a[mt], sA + row * GP + col * 2);
            }
            #pragma unroll
            for (int nb = 0; nb < 4; ++nb) {
                uint32_t bh[4];
                uint32_t row = wn * 64 + nb * 16 + ((lane >> 4) << 3) + (lane & 7);
                uint32_t col = kt * 16 + (lane & 8);
                ldsm_x4(bh, sBhi + row * GP + col * 2);
                if (PASSES == 2) {
                    uint32_t bl[4];
                    ldsm_x4(bl, sBlo + row * GP + col * 2);
                    #pragma unroll
                    for (int mt = 0; mt < 4; ++mt) {
                        mma_f16(acc[mt][2 * nb],     a[mt], bh[0], bh[1]);
                        mma_f16(acc[mt][2 * nb],     a[mt], bl[0], bl[1]);
                        mma_f16(acc[mt][2 * nb + 1], a[mt], bh[2], bh[3]);
                        mma_f16(acc[mt][2 * nb + 1], a[mt], bl[2], bl[3]);
                    }
                } else {
                    #pragma unroll
                    for (int mt = 0; mt < 4; ++mt) {
                        mma_f16(acc[mt][2 * nb],     a[mt], bh[0], bh[1]);
                        mma_f16(acc[mt][2 * nb + 1], a[mt], bh[2], bh[3]);
                    }
                }
            }
        }
        __syncthreads();
        if (it + 2 < 32) {
            gemm_load_stage<PASSES>(sb, st, t, A, Bhi, Blo, m0, n0, (it + 2) * 32);
            CP_COMMIT();
        } else {
            CP_COMMIT();  // keep group counts uniform
        }
    }

    // epilogue
    #pragma unroll
    for (int mt = 0; mt < 4; ++mt)
        #pragma unroll
        for (int nt = 0; nt < 8; ++nt) {
            int r = m0 + wm * 64 + mt * 16 + (lane >> 2);
            int c = n0 + wn * 64 + nt * 8 + (lane & 3) * 2;
            float v0 = acc[mt][nt][0], v1 = acc[mt][nt][1];
            float v2 = acc[mt][nt][2], v3 = acc[mt][nt][3];
            if (MODE == 0) {
                *reinterpret_cast<float2*>(Cf + (size_t)r * DD + c) = make_float2(v0, v1);
                *reinterpret_cast<float2*>(Cf + (size_t)(r + 8) * DD + c) = make_float2(v2, v3);
            } else if (MODE == 1) {
                *reinterpret_cast<uint32_t*>(Ch + (size_t)r * DD + c) = packh(v0, v1);
                *reinterpret_cast<uint32_t*>(Ch + (size_t)(r + 8) * DD + c) = packh(v2, v3);
            } else {
                float h0 = __half2float(__float2half_rn(v0));
                float h1 = __half2float(__float2half_rn(v1));
                float h2 = __half2float(__float2half_rn(v2));
                float h3 = __half2float(__float2half_rn(v3));
                *reinterpret_cast<uint32_t*>(Ch + (size_t)r * DD + c) = packh(h0, h1);
                *reinterpret_cast<uint32_t*>(Ch + (size_t)(r + 8) * DD + c) = packh(h2, h3);
                *reinterpret_cast<uint32_t*>(Cl + (size_t)r * DD + c) =
                    packh(v0 - h0, v1 - h1);
                *reinterpret_cast<uint32_t*>(Cl + (size_t)(r + 8) * DD + c) =
                    packh(v2 - h2, v3 - h3);
            }
        }
}

// ---------------- fused attention on mma.sync --------------------------------
// CTA = (128 q-rows, head, batch); 256 thr, warp = 16 q-rows.
// S = Qhi*K + Qlo*K (2-pass); w = exp2(S*C1 + bias*C2) via FFMA exp2;
// O += P*V single pass (P>=0, sums to 1 -> fp16 P error is ~1.4e-4 relative).
#define AP 144                    // smem pitch for 64-col fp16 tiles (+pad)
#define AMATB (128 * AP)          // 18432 B
#define A_SQHI 0
#define A_SQLO AMATB
#define A_KV0 (2 * AMATB)         // stage: K, V
#define A_STAGE (2 * AMATB)
#define A_SBIAS (A_KV0 + 2 * A_STAGE)
#define ATT_SMEM (A_SBIAS + 2 * 512)

__device__ __forceinline__ void attn_load_kv(
    uint32_t sb, int st, int t,
    const half_t* __restrict__ k16, const half_t* __restrict__ v16,
    const float* __restrict__ bias, size_t krow0, int hcol, size_t boff)
{
    uint32_t base = sb + A_KV0 + st * A_STAGE;
    #pragma unroll
    for (int i = 0; i < 4; ++i) {
        int ch = t + i * 256;          // 1024 chunks: 128 rows x 8 segs
        int row = ch >> 3, seg = ch & 7;
        size_t ga = (krow0 + row) * DD + hcol + seg * 8;
        uint32_t d = row * AP + seg * 16;
        cp16(base + d, k16 + ga);
        cp16(base + AMATB + d, v16 + ga);
    }
    if (t < 32) cp16(sb + A_SBIAS + st * 512 + t * 16, bias + boff + t * 4);
}

__global__ __launch_bounds__(256) void attn_mma(
    const half_t* __restrict__ qhi, const half_t* __restrict__ qlo,
    const half_t* __restrict__ k16, const half_t* __restrict__ v16,
    const float* __restrict__ bias, half_t* __restrict__ o16)
{
    extern __shared__ char smem[];
    const uint32_t sb = smem_u32(smem);
    const int t = threadIdx.x;
    const int lane = t & 31, wid = t >> 5;
    const int qt = blockIdx.x, h = blockIdx.y, b = blockIdx.z;
    const int hcol = h * DH;
    const size_t qrow0 = (size_t)b * QL + qt * 128;
    const size_t krowb = (size_t)b * KL;
    const float C1 = 0.125f * 1.44269504f;   // scale * log2(e)
    const float C2 = 1.44269504f;

    // load Q tile (hi/lo)
    #pragma unroll
    for (int i = 0; i < 4; ++i) {
        int ch = t + i * 256;
        int row = ch >> 3, seg = ch & 7;
        size_t ga = (qrow0 + row) * DD + hcol + seg * 8;
        uint32_t d = row * AP + seg * 16;
        cp16(sb + A_SQHI + d, qhi + ga);
        cp16(sb + A_SQLO + d, qlo + ga);
    }
    attn_load_kv(sb, 0, t, k16, v16, bias, krowb, hcol, krowb);
    CP_COMMIT();
    attn_load_kv(sb, 1, t, k16, v16, bias, krowb + 128, hcol, krowb + 128);
    CP_COMMIT();

    CP_WAIT1();
    __syncthreads();

    // Q fragments (resident)
    uint32_t qh[4][4], ql[4][4];
    #pragma unroll
    for (int dt = 0; dt < 4; ++dt) {
        uint32_t row = wid * 16 + (lane & 15);
        uint32_t col = dt * 16 + ((lane >> 4) << 3);
        ldsm_x4(qh[dt], sb + A_SQHI + row * AP + col * 2);
        ldsm_x4(ql[dt], sb + A_SQLO + row * AP + col * 2);
    }

    float oacc[8][4] = {};
    float l0 = 0.f, l1 = 0.f;

    for (int it = 0; it < 32; ++it) {
        if (it > 0) {
            if (it < 31) { CP_WAIT1(); } else { CP_WAIT0(); }
            __syncthreads();
        }
        const int st = it & 1;
        const uint32_t sK = sb + A_KV0 + st * A_STAGE;
        const uint32_t sV = sK + AMATB;

        // S = Q K^T  (2-pass: Qhi + Qlo); K frags via paired ldsm_x4
        float w[16][4] = {};
        #pragma unroll
        for (int dt = 0; dt < 4; ++dt) {
            #pragma unroll
            for (int np = 0; np < 8; ++np) {
                uint32_t kb[4];
                uint32_t row = np * 16 + ((lane >> 4) << 3) + (lane & 7);
                uint32_t col = dt * 16 + (lane & 8);
                ldsm_x4(kb, sK + row * AP + col * 2);
                mma_f16(w[2 * np],     qh[dt], kb[0], kb[1]);
                mma_f16(w[2 * np],     ql[dt], kb[0], kb[1]);
                mma_f16(w[2 * np + 1], qh[dt], kb[2], kb[3]);
                mma_f16(w[2 * np + 1], ql[dt], kb[2], kb[3]);
            }
        }

        // w = exp(S*scale + bias); accumulate row sums
        #pragma unroll
        for (int nt = 0; nt < 16; ++nt) {
            float2 bv = *reinterpret_cast<const float2*>(
                smem + A_SBIAS + st * 512 + (nt * 8 + (lane & 3) * 2) * 4);
            w[nt][0] = fexp2(fmaf(w[nt][0], C1, bv.x * C2));
            w[nt][1] = fexp2(fmaf(w[nt][1], C1, bv.y * C2));
            w[nt][2] = fexp2(fmaf(w[nt][2], C1, bv.x * C2));
            w[nt][3] = fexp2(fmaf(w[nt][3], C1, bv.y * C2));
            l0 += w[nt][0] + w[nt][1];
            l1 += w[nt][2] + w[nt][3];
        }

        // O += P V  (single pass: P rounded to fp16; V frags via ldsm_x4.trans)
        #pragma unroll
        for (int g = 0; g < 8; ++g) {
            uint32_t ph[4];
            ph[0] = packh(w[2 * g][0],     w[2 * g][1]);
            ph[1] = packh(w[2 * g][2],     w[2 * g][3]);
            ph[2] = packh(w[2 * g + 1][0], w[2 * g + 1][1]);
            ph[3] = packh(w[2 * g + 1][2], w[2 * g + 1][3]);
            #pragma unroll
            for (int np = 0; np < 4; ++np) {
                uint32_t vb[4];
                uint32_t row = g * 16 + (lane & 15);
                uint32_t col = np * 16 + ((lane >> 4) << 3);
                ldsm_x4t(vb, sV + row * AP + col * 2);
                mma_f16(oacc[2 * np],     ph, vb[0], vb[1]);
                mma_f16(oacc[2 * np + 1], ph, vb[2], vb[3]);
            }
        }

        __syncthreads();
        if (it + 2 < 32) {
            attn_load_kv(sb, st, t, k16, v16, bias,
                         krowb + (size_t)(it + 2) * 128, hcol,
                         krowb + (size_t)(it + 2) * 128);
            CP_COMMIT();
        } else {
            CP_COMMIT();
        }
    }

    // reduce row sums across the quad and normalize
    l0 += __shfl_xor_sync(0xffffffffu, l0, 1);
    l0 += __shfl_xor_sync(0xffffffffu, l0, 2);
    l1 += __shfl_xor_sync(0xffffffffu, l1, 1);
    l1 += __shfl_xor_sync(0xffffffffu, l1, 2);
    float inv0 = 1.0f / l0, inv1 = 1.0f / l1;

    size_t r0 = qrow0 + wid * 16 + (lane >> 2);
    size_t r1 = r0 + 8;
    #pragma unroll
    for (int nt = 0; nt < 8; ++nt) {
        int c = hcol + nt * 8 + (lane & 3) * 2;
        *reinterpret_cast<uint32_t*>(o16 + r0 * DD + c) =
            packh(oacc[nt][0] * inv0, oacc[nt][1] * inv0);
        *reinterpret_cast<uint32_t*>(o16 + r1 * DD + c) =
            packh(oacc[nt][2] * inv1, oacc[nt][3] * inv1);
    }
}

// ---------------- conversion kernels ----------------------------------------
__global__ void cvt16_kernel(const float4* __restrict__ x,
                             __half2* __restrict__ y, int n4)
{
    int i = blockIdx.x * blockDim.x + threadIdx.x;
    if (i >= n4) return;
    float4 v = x[i];
    y[2 * i]     = __floats2half2_rn(v.x, v.y);
    y[2 * i + 1] = __floats2half2_rn(v.z, v.w);
}

// 4x W[1024,1024] fp32 row-major -> W^T hi/lo fp16 [N,K], batched over z
__global__ void transpose_split4(const float* __restrict__ W0,
                                 const float* __restrict__ W1,
                                 const float* __restrict__ W2,
                                 const float* __restrict__ W3,
                                 half_t* __restrict__ Thi, half_t* __restrict__ Tlo)
{
    __shared__ float tl[32][33];
    const int tx = threadIdx.x, ty = threadIdx.y;
    const int n0 = blockIdx.x * 32, k0 = blockIdx.y * 32;
    const int z = blockIdx.z;
    const float* W = (z == 0) ? W0 : (z == 1) ? W1 : (z == 2) ? W2 : W3;
    half_t* th = Thi + (size_t)z * DD * DD;
    half_t* tlo = Tlo + (size_t)z * DD * DD;
    #pragma unroll
    for (int i = 0; i < 4; ++i)
        tl[ty + i * 8][tx] = W[(size_t)(k0 + ty + i * 8) * DD + n0 + tx];
    __syncthreads();
    #pragma unroll
    for (int i = 0; i < 4; ++i) {
        float v = tl[tx][ty + i * 8];  // = W[k0+tx][n0+ty+i*8]
        half_t hv = __float2half_rn(v);
        size_t idx = (size_t)(n0 + ty + i * 8) * DD + k0 + tx;
        th[idx] = hv;
        tlo[idx] = __float2half_rn(v - __half2float(hv));
    }
}

// ---------------- host launch -------------------------------------------------
extern "C" void kernel_launch(void* const* d_in, const int* in_sizes, int n_in,
                              void* d_out, int out_size)
{
    const float* query  = (const float*)d_in[0];
    const float* memory = (const float*)d_in[1];
    const float* bias   = (const float*)d_in[2];
    const float* W0 = (const float*)d_in[3];
    const float* W1 = (const float*)d_in[4];
    const float* W2 = (const float*)d_in[5];
    const float* W3 = (const float*)d_in[6];
    float* out = (float*)d_out;

    half_t *iq16, *im16, *wth, *wtl, *qh, *qlp, *k16, *v16, *a16;
    cudaGetSymbolAddress((void**)&iq16, gi_q16);
    cudaGetSymbolAddress((void**)&im16, gi_m16);
    cudaGetSymbolAddress((void**)&wth, g_wthi);
    cudaGetSymbolAddress((void**)&wtl, g_wtlo);
    cudaGetSymbolAddress((void**)&qh, g_qhi);
    cudaGetSymbolAddress((void**)&qlp, g_qlo);
    cudaGetSymbolAddress((void**)&k16, g_k16);
    cudaGetSymbolAddress((void**)&v16, g_v16);
    cudaGetSymbolAddress((void**)&a16, g_a16);

    static int attr_set = 0;
    if (!attr_set) {
        cudaFuncSetAttribute((const void*)gemm_mma<0, 2>,
                             cudaFuncAttributeMaxDynamicSharedMemorySize, GEMM_SMEM);
        cudaFuncSetAttribute((const void*)gemm_mma<1, 1>,
                             cudaFuncAttributeMaxDynamicSharedMemorySize, GEMM_SMEM);
        cudaFuncSetAttribute((const void*)gemm_mma<2, 2>,
                             cudaFuncAttributeMaxDynamicSharedMemorySize, GEMM_SMEM);
        cudaFuncSetAttribute((const void*)attn_mma,
                             cudaFuncAttributeMaxDynamicSharedMemorySize, ATT_SMEM);
        attr_set = 1;
    }

    // convert inputs to fp16
    {
        int n4 = (BB * QL * DD) / 4;
        cvt16_kernel<<<n4 / 256, 256>>>((const float4*)query, (__half2*)iq16, n4);
    }
    {
        int n4 = (BB * KL * DD) / 4;
        cvt16_kernel<<<n4 / 256, 256>>>((const float4*)memory, (__half2*)im16, n4);
    }
    // all 4 weight transpose+splits in one launch
    {
        dim3 thr(32, 8), grid(DD / 32, DD / 32, 4);
        transpose_split4<<<grid, thr>>>(W0, W1, W2, W3, wth, wtl);
    }

    // Q projection: 2-pass W, hi/lo fp16 out (feeds 2-pass QK)
    {
        dim3 grid(DD / 128, (BB * QL) / 128);
        gemm_mma<2, 2><<<grid, 128, GEMM_SMEM>>>(iq16, wth, wtl, nullptr, qh, qlp);
    }
    // K/V projections: SINGLE pass (Wk_hi / Wv_hi only), fp16 out
    {
        dim3 grid(DD / 128, (BB * KL) / 128);
        gemm_mma<1, 1><<<grid, 128, GEMM_SMEM>>>(im16, wth + (size_t)DD * DD,
                                                 wtl + (size_t)DD * DD, nullptr, k16, nullptr);
        gemm_mma<1, 1><<<grid, 128, GEMM_SMEM>>>(im16, wth + 2 * (size_t)DD * DD,
                                                 wtl + 2 * (size_t)DD * DD, nullptr, v16, nullptr);
    }
    // attention (QK 2-pass, PV single-pass)
    {
        dim3 grid(QL / 128, NH, BB);
        attn_mma<<<grid, 256, ATT_SMEM>>>(qh, qlp, k16, v16, bias, a16);
    }
    // O projection: 2-pass W -> fp32 out
    {
        dim3 grid(DD / 128, (BB * QL) / 128);
        gemm_mma<0, 2><<<grid, 128, GEMM_SMEM>>>(a16, wth + 3 * (size_t)DD * DD,
                                                 wtl + 3 * (size_t)DD * DD, out, nullptr,
                                                 nullptr);
    }
}